// round 13
// baseline (speedup 1.0000x reference)
#include <cuda_runtime.h>

#define TT 300
#define NB 4

// ---------------- static device buffers (masks padded +8 planes for prefetch) ----------------
__device__ unsigned long long g_r0[TT*NB*2*34];                      // input row masks, bit (x+2)
__device__ __align__(16) unsigned int g_M1[(TT+8)*NB*1156];          // spikes L1: 24ch bits / pixel
__device__ unsigned int g_M2[TT*NB*289];                             // spikes P1
__device__ __align__(16) unsigned int g_M3[(TT+8)*NB*289*2];         // spikes L2: 48ch in 2 words
__device__ unsigned int g_M4[TT*NB*81*2];                            // spikes P2
__device__ __align__(16) unsigned int g_M5[(TT+8)*NB*81*3];          // spikes L3: 96ch in 3 words
__device__ unsigned int g_M6[TT*NB*25*3];                            // spikes P3
__device__ unsigned int g_M7[TT*NB*8];                               // spikes dense1: 256 bits

__device__ float g_A1[(size_t)TT*NB*1156*32];                        // conv1 pre-act (pad 24->32)
__device__ float g_A2[(size_t)TT*NB*289*64];                         // conv2 pre-act (pad 48->64)
__device__ float g_A3[(size_t)TT*NB*81*96];                          // conv3 pre-act
__device__ __align__(16) float g_A7[TT*NB*256];                      // dense1 pre-act
__device__ float g_A8T[NB*16*TT];                                    // dense2 pre-act, [b][o][t]

// conv1: float4-packed padded table; one LDG.128 per event gives all 4 pixel weights.
__device__ float4 g_Wt1q[5*2*8*32];     // [ky][c][j:0..7][lane] -> (u=j, j+1, j+2, j+3), kx=u-3
// conv2/conv3: compact L1-resident tables (R10 form — padded variants thrashed L1)
__device__ float2 g_Wt2p[216*32];       // [(c*9+kt)][lane] -> (o=lane, o=lane+32)
__device__ float4 g_Wt3p[432*32];       // [(c*9+kt)][lane] -> (o=lane, +32, +64, pad)
__device__ __align__(16) float g_Wt4[2400*256];  // [(c*25+pos)][o 256]
__device__ float  g_Wt5[256*16];        // [i][o pad16]

// ---------------- SRM step: psp (tau=10) + spike w/ refractory (tau=1) ----------------
__device__ __forceinline__ float srm_step(float& p1, float& q1, float& p2, float& q2, float x) {
    const float A1 = 0.90483741803595952f;   // exp(-1/10)
    const float C1 = 0.27182818284590452f;   // e/10
    const float A2 = 0.36787944117144233f;   // exp(-1)
    const float C2 = 2.71828182845904523f;   // e
    const float RR = 20.0f * C2;             // SCALE_REF*THETA*c
    q1 = A1*q1 + A1*p1;
    p1 = A1*p1 + x;
    float y = C1 * q1;
    q2 = A2*q2 + A2*p2;
    float u = y - RR*q2;
    float s = (u >= 10.0f) ? 1.0f : 0.0f;
    p2 = A2*p2 + s;
    return s;
}

// ---------------- SRM scan: warp = 32 neurons, PF=12 rolling ring, 512-thr blocks ----------------
__device__ __forceinline__ void srm_scan_body(const float* __restrict__ in,
                                              unsigned int* __restrict__ out, int nW) {
    int w = blockIdx.x * 16 + (threadIdx.x >> 5);
    int lane = threadIdx.x & 31;
    if (w >= nW) return;
    size_t S = (size_t)nW * 32;
    const float* ip = in + (size_t)w*32 + lane;
    const int PF = 12;
    float buf[PF];
#pragma unroll
    for (int k = 0; k < PF; k++) buf[k] = ip[(size_t)k*S];
    const float* pf = ip + (size_t)PF*S;
    unsigned int* op = out + w;
    float p1=0,q1=0,p2=0,q2=0;
#pragma unroll 1
    for (int t0 = 0; t0 < TT - PF; t0 += PF) {          // 288 main steps
#pragma unroll
        for (int k = 0; k < PF; k++) {
            float x = buf[k];
            buf[k] = *pf; pf += S;                       // prefetch t+PF (max 299)
            float s = srm_step(p1, q1, p2, q2, x);
            unsigned bal = __ballot_sync(0xffffffffu, s > 0.5f);
            if (!lane) *op = bal;
            op += nW;
        }
    }
#pragma unroll
    for (int k = 0; k < PF; k++) {                       // t = 288..299
        float s = srm_step(p1, q1, p2, q2, buf[k]);
        unsigned bal = __ballot_sync(0xffffffffu, s > 0.5f);
        if (!lane) *op = bal;
        op += nW;
    }
}

__global__ void __launch_bounds__(512) srm_scan_L1() { srm_scan_body(g_A1, g_M1, NB*1156);  }
__global__ void __launch_bounds__(512) srm_scan_L2() { srm_scan_body(g_A2, g_M3, NB*289*2); }
__global__ void __launch_bounds__(512) srm_scan_L3() { srm_scan_body(g_A3, g_M5, NB*81*3);  }
__global__ void __launch_bounds__(512) srm_scan_D1() { srm_scan_body(g_A7, g_M7, NB*8);     }

// ---------------- init: weight tables ----------------
__global__ void init_weights(const float* __restrict__ Wc1, const float* __restrict__ Wc2,
                             const float* __restrict__ Wc3, const float* __restrict__ Wd4b) {
    int i = blockIdx.x * 256 + threadIdx.x;
    if (i < 5*2*8*32) {                                  // conv1 float4-packed padded table
        int q = i >> 5, o = i & 31;
        int ky = q / 16, rem = q % 16, c = rem / 8, j = rem % 8;
        float v[4];
#pragma unroll
        for (int d = 0; d < 4; d++) {
            int kx = j + d - 3;                          // u = j+d, kx = u-3
            v[d] = (o < 24 && kx >= 0 && kx < 5) ? Wc1[o*50 + c*25 + ky*5 + kx] : 0.f;
        }
        g_Wt1q[i] = make_float4(v[0], v[1], v[2], v[3]);
    }
    if (i < 216*32) {                                    // conv2 compact
        int tap = i >> 5, l = i & 31;
        float x = Wc2[l*216 + tap];
        float y = (l < 16) ? Wc2[(l + 32)*216 + tap] : 0.f;
        g_Wt2p[i] = make_float2(x, y);
    }
    if (i < 432*32) {                                    // conv3 compact
        int tap = i >> 5, l = i & 31;
        g_Wt3p[i] = make_float4(Wc3[l*432 + tap], Wc3[(l + 32)*432 + tap],
                                Wc3[(l + 64)*432 + tap], 0.f);
    }
    if (i < 256*16) {
        int r = i >> 4, o = i & 15;
        g_Wt5[i] = (o < 10) ? Wd4b[o*256 + r] : 0.f;
    }
}

// ---------------- pack s_in -> row bitmasks; warp=(b,c,y,t-chunk), lane=t: coalesced ----------------
__global__ void __launch_bounds__(512) pack_input(const float* __restrict__ s_in) {
    int w = blockIdx.x * 16 + (threadIdx.x >> 5);
    int lane = threadIdx.x & 31;
    if (w >= NB*2*34*10) return;
    int chunk = w % 10;
    int r = w / 10;
    int y = r % 34; r /= 34;
    int c = r % 2;
    int b = r / 2;
    int t = chunk * 32 + lane;
    bool tv = t < TT;
    const float* sp = s_in + ((size_t)((b*2 + c)*34 + y)*34)*TT + (tv ? t : 0);
    unsigned long long m = 0ull;
#pragma unroll
    for (int x = 0; x < 34; x++) {
        float v = sp[(size_t)x*TT];                      // lane-coalesced along t
        m |= (unsigned long long)(v != 0.f) << (x + 2);
    }
    if (tv) g_r0[((size_t)(t*NB + b)*2 + c)*34 + y] = m;
}

// ---------------- coalesced smem-tiled transpose of Wd4a -> g_Wt4 ----------------
__global__ void prep_wt4(const float* __restrict__ Wd4a) {
    __shared__ float tile[32][33];
    int r0 = blockIdx.x * 32, o0 = blockIdx.y * 32;
    int tx = threadIdx.x, ty = threadIdx.y;              // 32 x 8
#pragma unroll
    for (int j = 0; j < 32; j += 8)
        tile[ty + j][tx] = Wd4a[(size_t)(o0 + ty + j)*2400 + r0 + tx];   // coalesced in r
    __syncthreads();
#pragma unroll
    for (int j = 0; j < 32; j += 8)
        g_Wt4[(size_t)(r0 + ty + j)*256 + o0 + tx] = tile[tx][ty + j];   // coalesced in o
}

// ---------------- conv1 acc: warp per (t,b,x-QUAD), event-direct, float4 packed weights ----------------
__global__ void __launch_bounds__(256) conv1_acc() {
    int gw = blockIdx.x * 8 + (threadIdx.x >> 5);
    int lane = threadIdx.x & 31;
    if (gw >= TT*NB*306) return;                         // 34 rows x 9 quads
    int pr = gw % 306, tb = gw / 306;
    int y = pr / 9, x0 = (pr % 9) * 4;
    const unsigned long long* rt = g_r0 + (size_t)tb*68;
    const float4* wl = g_Wt1q + lane;
    float a0 = 0.f, a1 = 0.f, a2 = 0.f, a3 = 0.f;
#pragma unroll
    for (int ky = 0; ky < 5; ky++) {
        int yy = y + ky - 2;
        if (yy < 0 || yy >= 34) continue;
        unsigned w0 = (unsigned)(rt[yy] >> x0) & 0xFFu;        // taps for pixels x0..x0+3, c=0
        unsigned w1 = (unsigned)(rt[34 + yy] >> x0) & 0xFFu;   // c=1
        unsigned f = w0 | (w1 << 8);
        if (!f) continue;                                // early-out: common at 3% density
        const float4* wk = wl + ky*512;                  // ky*2*8*32
        do {
            int bit = __ffs(f) - 1; f &= f - 1;
            int c = bit >> 3, j = bit & 7;               // j = input col - x0
            float4 qv = wk[c*256 + (j << 5)];            // (w[u=j], w[j+1], w[j+2], w[j+3])
            a3 += qv.x;                                  // p=3: u=j
            a2 += qv.y;                                  // p=2: u=j+1
            a1 += qv.z;                                  // p=1: u=j+2
            a0 += qv.w;                                  // p=0: u=j+3
        } while (f);
    }
    size_t base = ((size_t)tb*1156 + y*34 + x0)*32;
    g_A1[base + lane]      = a0;
    g_A1[base + 32 + lane] = a1;
    if (x0 + 2 < 34) {                                   // last quad has only 2 valid pixels
        g_A1[base + 64 + lane] = a2;
        g_A1[base + 96 + lane] = a3;
    }
}

// ---------------- pool1 + SRM fused: warp per (b,opix), uint2 loads, PF=8, rolling ptrs ----------------
__global__ void __launch_bounds__(512) pool1_srm() {
    int w = blockIdx.x * 16 + (threadIdx.x >> 5);
    int lane = threadIdx.x & 31;
    if (w >= NB*289) return;
    int b = w / 289, pix = w % 289;
    int y = pix / 17, x = pix % 17;
    int p0 = b*1156 + 2*y*34 + 2*x;                      // even -> uint2 aligned
    const int ST = 2312;                                 // uint2 per t-plane
    const uint2* mA = (const uint2*)g_M1 + (p0 >> 1);
    const uint2* mB = mA + 17;
    uint2 bufA[8], bufB[8];
#pragma unroll
    for (int k = 0; k < 8; k++) { bufA[k] = mA[k*ST]; bufB[k] = mB[k*ST]; }
    const uint2* pA = mA + 8*ST;
    const uint2* pB = mB + 8*ST;
    unsigned int* op = g_M2 + w;
    float p1 = 0, q1 = 0, p2 = 0, q2 = 0;
#pragma unroll 1
    for (int t0 = 0; t0 < 296; t0 += 8) {
#pragma unroll
        for (int k = 0; k < 8; k++) {
            uint2 a = bufA[k], c = bufB[k];
            bufA[k] = *pA; pA += ST;                     // padded planes
            bufB[k] = *pB; pB += ST;
            int cnt = ((a.x >> lane) & 1) + ((a.y >> lane) & 1)
                    + ((c.x >> lane) & 1) + ((c.y >> lane) & 1);
            float s = srm_step(p1, q1, p2, q2, 11.0f * (float)cnt);
            unsigned bal = __ballot_sync(0xffffffffu, s > 0.5f);
            if (!lane) *op = bal;
            op += NB*289;
        }
    }
#pragma unroll
    for (int k = 0; k < 4; k++) {                        // t = 296..299
        int cnt = ((bufA[k].x >> lane) & 1) + ((bufA[k].y >> lane) & 1)
                + ((bufB[k].x >> lane) & 1) + ((bufB[k].y >> lane) & 1);
        float s = srm_step(p1, q1, p2, q2, 11.0f * (float)cnt);
        unsigned bal = __ballot_sync(0xffffffffu, s > 0.5f);
        if (!lane) *op = bal;
        op += NB*289;
    }
}

// ---------------- conv2 acc (24->48, 3x3, pad1, 17x17): warp per (t,b,x-PAIR), compact weights ----------------
__global__ void __launch_bounds__(256) conv2_acc() {
    int gw = blockIdx.x * 8 + (threadIdx.x >> 5);
    int lane = threadIdx.x & 31;
    if (gw >= TT*NB*153) return;                         // 17 rows x 9 pairs
    int pr = gw % 153, tb = gw / 153;
    int y = pr / 9, x0 = (pr % 9) * 2;
    bool x1v = (x0 + 1) < 17;
    const unsigned* mm = g_M2 + (size_t)tb*289;
    float aa0 = 0.f, ab0 = 0.f, aa1 = 0.f, ab1 = 0.f;
#pragma unroll
    for (int ky = 0; ky < 3; ky++) {
        int yy = y + ky - 1;
        if (yy < 0 || yy >= 17) continue;
        const unsigned* row = mm + yy*17;
#pragma unroll
        for (int xi = 0; xi < 4; xi++) {                 // input cols x0-1 .. x0+2
            int xx = x0 - 1 + xi;
            unsigned m = 0u;
            if (xx >= 0 && xx < 17 && (xi < 3 || x1v)) m = row[xx];
            while (m) {
                int c = __ffs(m) - 1; m &= m - 1;
                const float2* wb = g_Wt2p + c*288 + lane;     // c*9*32
                if (xi < 3) {                                 // pixel0: kt = ky*3+xi
                    float2 wv = wb[(ky*3 + xi)*32];
                    aa0 += wv.x; ab0 += wv.y;
                }
                if (xi >= 1 && x1v) {                         // pixel1: kt = ky*3+xi-1
                    float2 wv = wb[(ky*3 + xi - 1)*32];
                    aa1 += wv.x; ab1 += wv.y;
                }
            }
        }
    }
    size_t base = ((size_t)tb*289 + y*17 + x0)*64;
    g_A2[base + lane]      = aa0;
    g_A2[base + 32 + lane] = ab0;
    if (x1v) {
        g_A2[base + 64 + lane] = aa1;
        g_A2[base + 96 + lane] = ab1;
    }
}

// ---------------- pool2 + SRM fused: warp per (b,opix,half), PF=8, rolling ptrs ----------------
__global__ void __launch_bounds__(512) pool2_srm() {
    int w = blockIdx.x * 16 + (threadIdx.x >> 5);
    int lane = threadIdx.x & 31;
    if (w >= NB*162) return;
    int b = w / 162, r = w % 162, pix = r >> 1, half = r & 1;
    int y = pix / 9, x = pix % 9;
    bool xv = (2*x + 1) < 17, yv = (2*y + 1) < 17;
    const int ST = 2312;                                 // words per t-plane
    const unsigned* m0 = g_M3 + b*578 + (2*y*17 + 2*x)*2 + half;
    const unsigned* m1 = m0 + 2;
    const unsigned* m2 = m0 + 34;
    const unsigned* m3 = m0 + 36;
    unsigned buf[8][4];
#pragma unroll
    for (int k = 0; k < 8; k++) {
        buf[k][0] = m0[k*ST];
        buf[k][1] = xv ? m1[k*ST] : 0u;
        buf[k][2] = yv ? m2[k*ST] : 0u;
        buf[k][3] = (xv && yv) ? m3[k*ST] : 0u;
    }
    const unsigned *p0 = m0 + 8*ST, *p1p = m1 + 8*ST, *p2p = m2 + 8*ST, *p3p = m3 + 8*ST;
    unsigned int* op = g_M4 + w;
    float p1 = 0, q1 = 0, p2 = 0, q2 = 0;
#pragma unroll 1
    for (int t0 = 0; t0 < 296; t0 += 8) {
#pragma unroll
        for (int k = 0; k < 8; k++) {
            int cnt = ((buf[k][0] >> lane) & 1) + ((buf[k][1] >> lane) & 1)
                    + ((buf[k][2] >> lane) & 1) + ((buf[k][3] >> lane) & 1);
            buf[k][0] = *p0; p0 += ST;
            buf[k][1] = xv ? *p1p : 0u; p1p += ST;
            buf[k][2] = yv ? *p2p : 0u; p2p += ST;
            buf[k][3] = (xv && yv) ? *p3p : 0u; p3p += ST;
            float s = srm_step(p1, q1, p2, q2, 11.0f * (float)cnt);
            unsigned bal = __ballot_sync(0xffffffffu, s > 0.5f);
            if (!lane) *op = bal;
            op += NB*162;
        }
    }
#pragma unroll
    for (int k = 0; k < 4; k++) {
        int cnt = ((buf[k][0] >> lane) & 1) + ((buf[k][1] >> lane) & 1)
                + ((buf[k][2] >> lane) & 1) + ((buf[k][3] >> lane) & 1);
        float s = srm_step(p1, q1, p2, q2, 11.0f * (float)cnt);
        unsigned bal = __ballot_sync(0xffffffffu, s > 0.5f);
        if (!lane) *op = bal;
        op += NB*162;
    }
}

// ---------------- conv3 acc (48->96, 3x3, pad1, 9x9): warp per (t,b,x-PAIR), compact weights ----------------
__global__ void __launch_bounds__(256) conv3_acc() {
    int gw = blockIdx.x * 8 + (threadIdx.x >> 5);
    int lane = threadIdx.x & 31;
    if (gw >= TT*NB*45) return;                          // 9 rows x 5 pairs
    int pr = gw % 45, tb = gw / 45;
    int y = pr / 5, x0 = (pr % 5) * 2;
    bool x1v = (x0 + 1) < 9;
    const unsigned* mm = g_M4 + (size_t)tb*162;
    float a00 = 0.f, a01 = 0.f, a02 = 0.f;
    float a10 = 0.f, a11 = 0.f, a12 = 0.f;
#pragma unroll
    for (int ky = 0; ky < 3; ky++) {
        int yy = y + ky - 1;
        if (yy < 0 || yy >= 9) continue;
        const unsigned* row = mm + yy*18;
#pragma unroll
        for (int xi = 0; xi < 4; xi++) {                 // input cols x0-1 .. x0+2
            int xx = x0 - 1 + xi;
            unsigned mlo = 0u, mhi = 0u;
            if (xx >= 0 && xx < 9 && (xi < 3 || x1v)) {
                mlo = row[xx*2];
                mhi = row[xx*2 + 1];
            }
            while (mlo) {
                int c = __ffs(mlo) - 1; mlo &= mlo - 1;
                const float4* wb = g_Wt3p + c*288 + lane;
                if (xi < 3) {
                    float4 wv = wb[(ky*3 + xi)*32];
                    a00 += wv.x; a01 += wv.y; a02 += wv.z;
                }
                if (xi >= 1 && x1v) {
                    float4 wv = wb[(ky*3 + xi - 1)*32];
                    a10 += wv.x; a11 += wv.y; a12 += wv.z;
                }
            }
            while (mhi) {
                int c = __ffs(mhi) - 1; mhi &= mhi - 1;
                const float4* wb = g_Wt3p + (c + 32)*288 + lane;
                if (xi < 3) {
                    float4 wv = wb[(ky*3 + xi)*32];
                    a00 += wv.x; a01 += wv.y; a02 += wv.z;
                }
                if (xi >= 1 && x1v) {
                    float4 wv = wb[(ky*3 + xi - 1)*32];
                    a10 += wv.x; a11 += wv.y; a12 += wv.z;
                }
            }
        }
    }
    size_t base = ((size_t)tb*81 + y*9 + x0)*96;
    g_A3[base + lane]      = a00;
    g_A3[base + 32 + lane] = a01;
    g_A3[base + 64 + lane] = a02;
    if (x1v) {
        g_A3[base + 96 + lane]  = a10;
        g_A3[base + 128 + lane] = a11;
        g_A3[base + 160 + lane] = a12;
    }
}

// ---------------- pool3 + SRM fused: warp per (b,opix,wrd), PF=8, rolling ptrs ----------------
__global__ void __launch_bounds__(512) pool3_srm() {
    int w = blockIdx.x * 16 + (threadIdx.x >> 5);
    int lane = threadIdx.x & 31;
    if (w >= NB*75) return;
    int b = w / 75, r = w % 75, pix = r / 3, wrd = r % 3;
    int y = pix / 5, x = pix % 5;
    bool xv = (2*x + 1) < 9, yv = (2*y + 1) < 9;
    const int ST = 972;                                  // words per t-plane
    const unsigned* m0 = g_M5 + b*243 + (2*y*9 + 2*x)*3 + wrd;
    const unsigned* m1 = m0 + 3;
    const unsigned* m2 = m0 + 27;
    const unsigned* m3 = m0 + 30;
    unsigned buf[8][4];
#pragma unroll
    for (int k = 0; k < 8; k++) {
        buf[k][0] = m0[k*ST];
        buf[k][1] = xv ? m1[k*ST] : 0u;
        buf[k][2] = yv ? m2[k*ST] : 0u;
        buf[k][3] = (xv && yv) ? m3[k*ST] : 0u;
    }
    const unsigned *p0 = m0 + 8*ST, *p1p = m1 + 8*ST, *p2p = m2 + 8*ST, *p3p = m3 + 8*ST;
    unsigned int* op = g_M6 + w;
    float p1 = 0, q1 = 0, p2 = 0, q2 = 0;
#pragma unroll 1
    for (int t0 = 0; t0 < 296; t0 += 8) {
#pragma unroll
        for (int k = 0; k < 8; k++) {
            int cnt = ((buf[k][0] >> lane) & 1) + ((buf[k][1] >> lane) & 1)
                    + ((buf[k][2] >> lane) & 1) + ((buf[k][3] >> lane) & 1);
            buf[k][0] = *p0; p0 += ST;
            buf[k][1] = xv ? *p1p : 0u; p1p += ST;
            buf[k][2] = yv ? *p2p : 0u; p2p += ST;
            buf[k][3] = (xv && yv) ? *p3p : 0u; p3p += ST;
            float s = srm_step(p1, q1, p2, q2, 11.0f * (float)cnt);
            unsigned bal = __ballot_sync(0xffffffffu, s > 0.5f);
            if (!lane) *op = bal;
            op += NB*75;
        }
    }
#pragma unroll
    for (int k = 0; k < 4; k++) {
        int cnt = ((buf[k][0] >> lane) & 1) + ((buf[k][1] >> lane) & 1)
                + ((buf[k][2] >> lane) & 1) + ((buf[k][3] >> lane) & 1);
        float s = srm_step(p1, q1, p2, q2, 11.0f * (float)cnt);
        unsigned bal = __ballot_sync(0xffffffffu, s > 0.5f);
        if (!lane) *op = bal;
        op += NB*75;
    }
}

// ---------------- dense1 (2400->256): WARP per (t,b), float4 weight rows ----------------
__global__ void __launch_bounds__(256) dense1() {
    int w = blockIdx.x * 8 + (threadIdx.x >> 5);
    int lane = threadIdx.x & 31;
    if (w >= TT*NB) return;
    const unsigned* m = g_M6 + (size_t)w*75;
    float4 acc0 = make_float4(0.f, 0.f, 0.f, 0.f);
    float4 acc1 = make_float4(0.f, 0.f, 0.f, 0.f);
    int pw = 0;
    for (int pos = 0; pos < 25; pos++) {
#pragma unroll
        for (int wrd = 0; wrd < 3; wrd++) {
            unsigned mm = m[pw++];
            int cb = wrd*32;
            while (mm) {
                int c = cb + __ffs(mm) - 1; mm &= mm - 1;
                const float4* wr = (const float4*)(g_Wt4 + (size_t)(c*25 + pos)*256) + lane;
                float4 v0 = wr[0], v1 = wr[32];
                acc0.x += v0.x; acc0.y += v0.y; acc0.z += v0.z; acc0.w += v0.w;
                acc1.x += v1.x; acc1.y += v1.y; acc1.z += v1.z; acc1.w += v1.w;
            }
        }
    }
    float4* op = (float4*)(g_A7 + (size_t)w*256) + lane;
    op[0]  = acc0;
    op[32] = acc1;
}

// ---------------- dense2 (256->10): warp per (t,b), writes transposed ----------------
__global__ void __launch_bounds__(256) dense2() {
    int w = blockIdx.x * 8 + (threadIdx.x >> 5);
    int lane = threadIdx.x & 31;
    if (w >= TT*NB) return;
    int t = w / NB, b = w % NB;
    if (lane < 16) {
        const unsigned* m = g_M7 + (size_t)w*8;
        float acc = 0.f;
        for (int wd = 0; wd < 8; wd++) {
            unsigned mm = m[wd];
            int ib = wd*32;
            while (mm) { int i = ib + __ffs(mm) - 1; mm &= mm - 1; acc += g_Wt5[i*16 + lane]; }
        }
        g_A8T[(size_t)(b*16 + lane)*TT + t] = acc;
    }
}

// ---------------- final SRM -> output spikes (B,10,T) ----------------
__global__ void srm_out(float* __restrict__ out) {
    int tid = threadIdx.x;
    if (tid >= 40) return;
    int b = tid / 10, o = tid % 10;
    const float* ip = g_A8T + (size_t)(b*16 + o)*TT;
    const int PF = 8;
    float buf[PF];
#pragma unroll
    for (int k = 0; k < PF; k++) buf[k] = ip[k];
    float p1 = 0, q1 = 0, p2 = 0, q2 = 0;
    float* op = out + (size_t)(b*10 + o)*TT;
    for (int t0 = 0; t0 < TT; t0 += PF) {
#pragma unroll
        for (int k = 0; k < PF; k++) {
            int t = t0 + k;
            if (t >= TT) break;
            float x = buf[k];
            int tn = t + PF;
            buf[k] = (tn < TT) ? ip[tn] : 0.f;
            op[t] = srm_step(p1, q1, p2, q2, x);
        }
    }
}

extern "C" void kernel_launch(void* const* d_in, const int* in_sizes, int n_in,
                              void* d_out, int out_size) {
    const float* s_in = (const float*)d_in[0];
    const float* Wc1  = (const float*)d_in[1];
    const float* Wc2  = (const float*)d_in[2];
    const float* Wc3  = (const float*)d_in[3];
    const float* Wd4a = (const float*)d_in[4];
    const float* Wd4b = (const float*)d_in[5];
    float* out = (float*)d_out;

    // slots 0..2 so conv1_acc lands in the profiled 4th slot
    init_weights<<<54, 256>>>(Wc1, Wc2, Wc3, Wd4b);
    pack_input<<<(NB*2*34*10 + 15)/16, 512>>>(s_in);
    prep_wt4<<<dim3(75, 8), dim3(32, 8)>>>(Wd4a);

    conv1_acc<<<(TT*NB*306 + 7)/8, 256>>>();
    srm_scan_L1<<<(NB*1156 + 15)/16, 512>>>();
    pool1_srm<<<(NB*289 + 15)/16, 512>>>();

    conv2_acc<<<(TT*NB*153 + 7)/8, 256>>>();
    srm_scan_L2<<<(NB*289*2 + 15)/16, 512>>>();
    pool2_srm<<<(NB*162 + 15)/16, 512>>>();

    conv3_acc<<<(TT*NB*45 + 7)/8, 256>>>();
    srm_scan_L3<<<(NB*81*3 + 15)/16, 512>>>();
    pool3_srm<<<(NB*75 + 15)/16, 512>>>();

    dense1<<<(TT*NB + 7)/8, 256>>>();
    srm_scan_D1<<<2, 512>>>();

    dense2<<<(TT*NB + 7)/8, 256>>>();
    srm_out<<<1, 64>>>(out);
}

// round 14
// speedup vs baseline: 1.4500x; 1.4500x over previous
#include <cuda_runtime.h>

#define TT 300
#define NB 4

// ---------------- static device buffers (masks padded +8 planes for prefetch) ----------------
__device__ unsigned long long g_r0[TT*NB*2*34];                      // input row masks, bit (x+2)
__device__ __align__(16) unsigned int g_M1[(TT+8)*NB*1156];          // spikes L1: 24ch bits / pixel
__device__ unsigned int g_M2[TT*NB*289];                             // spikes P1
__device__ __align__(16) unsigned int g_M3[(TT+8)*NB*289*2];         // spikes L2: 48ch in 2 words
__device__ unsigned int g_M4[TT*NB*81*2];                            // spikes P2
__device__ __align__(16) unsigned int g_M5[(TT+8)*NB*81*3];          // spikes L3: 96ch in 3 words
__device__ unsigned int g_M6[TT*NB*25*3];                            // spikes P3
__device__ unsigned int g_M7[TT*NB*8];                               // spikes dense1: 256 bits

__device__ float g_A1[(size_t)TT*NB*1156*32];                        // conv1 pre-act (pad 24->32)
__device__ float g_A2[(size_t)TT*NB*289*64];                         // conv2 pre-act (pad 48->64)
__device__ float g_A3[(size_t)TT*NB*81*96];                          // conv3 pre-act
__device__ __align__(16) float g_A7[TT*NB*256];                      // dense1 pre-act
__device__ float g_A8T[NB*16*TT];                                    // dense2 pre-act, [b][o][t]

// conv1: SCALAR zero-padded table (44 KB, L1-resident; measured best at 77us)
__device__ float  g_Wt1x[5*2*11*32];    // [ky][c][u=kx+3: 0..10][o pad32]
// conv2/conv3: compact L1-resident tables (padded variants thrashed L1)
__device__ float2 g_Wt2p[216*32];       // [(c*9+kt)][lane] -> (o=lane, o=lane+32)
__device__ float4 g_Wt3p[432*32];       // [(c*9+kt)][lane] -> (o=lane, +32, +64, pad)
__device__ __align__(16) float g_Wt4[2400*256];  // [(c*25+pos)][o 256]
__device__ float  g_Wt5[256*16];        // [i][o pad16]

// ---------------- SRM step: psp (tau=10) + spike w/ refractory (tau=1) ----------------
__device__ __forceinline__ float srm_step(float& p1, float& q1, float& p2, float& q2, float x) {
    const float A1 = 0.90483741803595952f;   // exp(-1/10)
    const float C1 = 0.27182818284590452f;   // e/10
    const float A2 = 0.36787944117144233f;   // exp(-1)
    const float C2 = 2.71828182845904523f;   // e
    const float RR = 20.0f * C2;             // SCALE_REF*THETA*c
    q1 = A1*q1 + A1*p1;
    p1 = A1*p1 + x;
    float y = C1 * q1;
    q2 = A2*q2 + A2*p2;
    float u = y - RR*q2;
    float s = (u >= 10.0f) ? 1.0f : 0.0f;
    p2 = A2*p2 + s;
    return s;
}

// ---------------- SRM scan: warp = 32 neurons, PF=12 rolling ring, 512-thr blocks ----------------
__device__ __forceinline__ void srm_scan_body(const float* __restrict__ in,
                                              unsigned int* __restrict__ out, int nW) {
    int w = blockIdx.x * 16 + (threadIdx.x >> 5);
    int lane = threadIdx.x & 31;
    if (w >= nW) return;
    size_t S = (size_t)nW * 32;
    const float* ip = in + (size_t)w*32 + lane;
    const int PF = 12;
    float buf[PF];
#pragma unroll
    for (int k = 0; k < PF; k++) buf[k] = ip[(size_t)k*S];
    const float* pf = ip + (size_t)PF*S;
    unsigned int* op = out + w;
    float p1=0,q1=0,p2=0,q2=0;
#pragma unroll 1
    for (int t0 = 0; t0 < TT - PF; t0 += PF) {          // 288 main steps
#pragma unroll
        for (int k = 0; k < PF; k++) {
            float x = buf[k];
            buf[k] = *pf; pf += S;                       // prefetch t+PF (max 299)
            float s = srm_step(p1, q1, p2, q2, x);
            unsigned bal = __ballot_sync(0xffffffffu, s > 0.5f);
            if (!lane) *op = bal;
            op += nW;
        }
    }
#pragma unroll
    for (int k = 0; k < PF; k++) {                       // t = 288..299
        float s = srm_step(p1, q1, p2, q2, buf[k]);
        unsigned bal = __ballot_sync(0xffffffffu, s > 0.5f);
        if (!lane) *op = bal;
        op += nW;
    }
}

__global__ void __launch_bounds__(512) srm_scan_L1() { srm_scan_body(g_A1, g_M1, NB*1156);  }
__global__ void __launch_bounds__(512) srm_scan_L2() { srm_scan_body(g_A2, g_M3, NB*289*2); }
__global__ void __launch_bounds__(512) srm_scan_L3() { srm_scan_body(g_A3, g_M5, NB*81*3);  }
__global__ void __launch_bounds__(512) srm_scan_D1() { srm_scan_body(g_A7, g_M7, NB*8);     }

// ---------------- init: weight tables ----------------
__global__ void init_weights(const float* __restrict__ Wc1, const float* __restrict__ Wc2,
                             const float* __restrict__ Wc3, const float* __restrict__ Wd4b) {
    int i = blockIdx.x * 256 + threadIdx.x;
    if (i < 5*2*11*32) {                                 // conv1 scalar padded table
        int q = i >> 5, o = i & 31;
        int ky = q / 22, rem = q % 22, c = rem / 11, u = rem % 11;
        int kx = u - 3;
        g_Wt1x[i] = (o < 24 && kx >= 0 && kx < 5) ? Wc1[o*50 + c*25 + ky*5 + kx] : 0.f;
    }
    if (i < 216*32) {                                    // conv2 compact
        int tap = i >> 5, l = i & 31;
        float x = Wc2[l*216 + tap];
        float y = (l < 16) ? Wc2[(l + 32)*216 + tap] : 0.f;
        g_Wt2p[i] = make_float2(x, y);
    }
    if (i < 432*32) {                                    // conv3 compact
        int tap = i >> 5, l = i & 31;
        g_Wt3p[i] = make_float4(Wc3[l*432 + tap], Wc3[(l + 32)*432 + tap],
                                Wc3[(l + 64)*432 + tap], 0.f);
    }
    if (i < 256*16) {
        int r = i >> 4, o = i & 15;
        g_Wt5[i] = (o < 10) ? Wd4b[o*256 + r] : 0.f;
    }
}

// ---------------- pack s_in -> row bitmasks; warp=(b,c,y,t-chunk), lane=t: coalesced ----------------
__global__ void __launch_bounds__(512) pack_input(const float* __restrict__ s_in) {
    int w = blockIdx.x * 16 + (threadIdx.x >> 5);
    int lane = threadIdx.x & 31;
    if (w >= NB*2*34*10) return;
    int chunk = w % 10;
    int r = w / 10;
    int y = r % 34; r /= 34;
    int c = r % 2;
    int b = r / 2;
    int t = chunk * 32 + lane;
    bool tv = t < TT;
    const float* sp = s_in + ((size_t)((b*2 + c)*34 + y)*34)*TT + (tv ? t : 0);
    unsigned long long m = 0ull;
#pragma unroll
    for (int x = 0; x < 34; x++) {
        float v = sp[(size_t)x*TT];                      // lane-coalesced along t
        m |= (unsigned long long)(v != 0.f) << (x + 2);
    }
    if (tv) g_r0[((size_t)(t*NB + b)*2 + c)*34 + y] = m;
}

// ---------------- coalesced smem-tiled transpose of Wd4a -> g_Wt4 ----------------
__global__ void prep_wt4(const float* __restrict__ Wd4a) {
    __shared__ float tile[32][33];
    int r0 = blockIdx.x * 32, o0 = blockIdx.y * 32;
    int tx = threadIdx.x, ty = threadIdx.y;              // 32 x 8
#pragma unroll
    for (int j = 0; j < 32; j += 8)
        tile[ty + j][tx] = Wd4a[(size_t)(o0 + ty + j)*2400 + r0 + tx];   // coalesced in r
    __syncthreads();
#pragma unroll
    for (int j = 0; j < 32; j += 8)
        g_Wt4[(size_t)(r0 + ty + j)*256 + o0 + tx] = tile[tx][ty + j];   // coalesced in o
}

// ---------------- conv1 acc: warp per (t,b,x-QUAD), event-direct, scalar padded weights ----------------
__global__ void __launch_bounds__(256) conv1_acc() {
    int gw = blockIdx.x * 8 + (threadIdx.x >> 5);
    int lane = threadIdx.x & 31;
    if (gw >= TT*NB*306) return;                         // 34 rows x 9 quads
    int pr = gw % 306, tb = gw / 306;
    int y = pr / 9, x0 = (pr % 9) * 4;
    const unsigned long long* rt = g_r0 + (size_t)tb*68;
    const float* wl = g_Wt1x + lane;
    float a0 = 0.f, a1 = 0.f, a2 = 0.f, a3 = 0.f;
#pragma unroll
    for (int ky = 0; ky < 5; ky++) {
        int yy = y + ky - 2;
        if (yy < 0 || yy >= 34) continue;
        unsigned w0 = (unsigned)(rt[yy] >> x0) & 0xFFu;        // taps for pixels x0..x0+3, c=0
        unsigned w1 = (unsigned)(rt[34 + yy] >> x0) & 0xFFu;   // c=1
        unsigned f = w0 | (w1 << 8);
        if (!f) continue;                                // early-out: common at 3% density
        const float* wk = wl + ky*704;                   // ky*2*11*32
        do {
            int bit = __ffs(f) - 1; f &= f - 1;
            int c = bit >> 3, j = bit & 7;               // j = input col - x0
            const float* wr = wk + c*352 + (j << 5);     // slot u=j (kx = j - p -> u = j-p+3)
            a3 += wr[0];                                 // p=3: u=j
            a2 += wr[32];                                // p=2: u=j+1
            a1 += wr[64];                                // p=1: u=j+2
            a0 += wr[96];                                // p=0: u=j+3
        } while (f);
    }
    size_t base = ((size_t)tb*1156 + y*34 + x0)*32;
    g_A1[base + lane]      = a0;
    g_A1[base + 32 + lane] = a1;
    if (x0 + 2 < 34) {                                   // last quad has only 2 valid pixels
        g_A1[base + 64 + lane] = a2;
        g_A1[base + 96 + lane] = a3;
    }
}

// ---------------- pool1 + SRM fused: warp per (b,opix), uint2 loads, PF=8, rolling ptrs ----------------
__global__ void __launch_bounds__(512) pool1_srm() {
    int w = blockIdx.x * 16 + (threadIdx.x >> 5);
    int lane = threadIdx.x & 31;
    if (w >= NB*289) return;
    int b = w / 289, pix = w % 289;
    int y = pix / 17, x = pix % 17;
    int p0 = b*1156 + 2*y*34 + 2*x;                      // even -> uint2 aligned
    const int ST = 2312;                                 // uint2 per t-plane
    const uint2* mA = (const uint2*)g_M1 + (p0 >> 1);
    const uint2* mB = mA + 17;
    uint2 bufA[8], bufB[8];
#pragma unroll
    for (int k = 0; k < 8; k++) { bufA[k] = mA[k*ST]; bufB[k] = mB[k*ST]; }
    const uint2* pA = mA + 8*ST;
    const uint2* pB = mB + 8*ST;
    unsigned int* op = g_M2 + w;
    float p1 = 0, q1 = 0, p2 = 0, q2 = 0;
#pragma unroll 1
    for (int t0 = 0; t0 < 296; t0 += 8) {
#pragma unroll
        for (int k = 0; k < 8; k++) {
            uint2 a = bufA[k], c = bufB[k];
            bufA[k] = *pA; pA += ST;                     // padded planes
            bufB[k] = *pB; pB += ST;
            int cnt = ((a.x >> lane) & 1) + ((a.y >> lane) & 1)
                    + ((c.x >> lane) & 1) + ((c.y >> lane) & 1);
            float s = srm_step(p1, q1, p2, q2, 11.0f * (float)cnt);
            unsigned bal = __ballot_sync(0xffffffffu, s > 0.5f);
            if (!lane) *op = bal;
            op += NB*289;
        }
    }
#pragma unroll
    for (int k = 0; k < 4; k++) {                        // t = 296..299
        int cnt = ((bufA[k].x >> lane) & 1) + ((bufA[k].y >> lane) & 1)
                + ((bufB[k].x >> lane) & 1) + ((bufB[k].y >> lane) & 1);
        float s = srm_step(p1, q1, p2, q2, 11.0f * (float)cnt);
        unsigned bal = __ballot_sync(0xffffffffu, s > 0.5f);
        if (!lane) *op = bal;
        op += NB*289;
    }
}

// ---------------- conv2 acc (24->48, 3x3, pad1, 17x17): warp per (t,b,x-PAIR), compact weights ----------------
__global__ void __launch_bounds__(256) conv2_acc() {
    int gw = blockIdx.x * 8 + (threadIdx.x >> 5);
    int lane = threadIdx.x & 31;
    if (gw >= TT*NB*153) return;                         // 17 rows x 9 pairs
    int pr = gw % 153, tb = gw / 153;
    int y = pr / 9, x0 = (pr % 9) * 2;
    bool x1v = (x0 + 1) < 17;
    const unsigned* mm = g_M2 + (size_t)tb*289;
    float aa0 = 0.f, ab0 = 0.f, aa1 = 0.f, ab1 = 0.f;
#pragma unroll
    for (int ky = 0; ky < 3; ky++) {
        int yy = y + ky - 1;
        if (yy < 0 || yy >= 17) continue;
        const unsigned* row = mm + yy*17;
#pragma unroll
        for (int xi = 0; xi < 4; xi++) {                 // input cols x0-1 .. x0+2
            int xx = x0 - 1 + xi;
            unsigned m = 0u;
            if (xx >= 0 && xx < 17 && (xi < 3 || x1v)) m = row[xx];
            while (m) {
                int c = __ffs(m) - 1; m &= m - 1;
                const float2* wb = g_Wt2p + c*288 + lane;     // c*9*32
                if (xi < 3) {                                 // pixel0: kt = ky*3+xi
                    float2 wv = wb[(ky*3 + xi)*32];
                    aa0 += wv.x; ab0 += wv.y;
                }
                if (xi >= 1 && x1v) {                         // pixel1: kt = ky*3+xi-1
                    float2 wv = wb[(ky*3 + xi - 1)*32];
                    aa1 += wv.x; ab1 += wv.y;
                }
            }
        }
    }
    size_t base = ((size_t)tb*289 + y*17 + x0)*64;
    g_A2[base + lane]      = aa0;
    g_A2[base + 32 + lane] = ab0;
    if (x1v) {
        g_A2[base + 64 + lane] = aa1;
        g_A2[base + 96 + lane] = ab1;
    }
}

// ---------------- pool2 + SRM fused: warp per (b,opix,half), PF=8, rolling ptrs ----------------
__global__ void __launch_bounds__(512) pool2_srm() {
    int w = blockIdx.x * 16 + (threadIdx.x >> 5);
    int lane = threadIdx.x & 31;
    if (w >= NB*162) return;
    int b = w / 162, r = w % 162, pix = r >> 1, half = r & 1;
    int y = pix / 9, x = pix % 9;
    bool xv = (2*x + 1) < 17, yv = (2*y + 1) < 17;
    const int ST = 2312;                                 // words per t-plane
    const unsigned* m0 = g_M3 + b*578 + (2*y*17 + 2*x)*2 + half;
    const unsigned* m1 = m0 + 2;
    const unsigned* m2 = m0 + 34;
    const unsigned* m3 = m0 + 36;
    unsigned buf[8][4];
#pragma unroll
    for (int k = 0; k < 8; k++) {
        buf[k][0] = m0[k*ST];
        buf[k][1] = xv ? m1[k*ST] : 0u;
        buf[k][2] = yv ? m2[k*ST] : 0u;
        buf[k][3] = (xv && yv) ? m3[k*ST] : 0u;
    }
    const unsigned *p0 = m0 + 8*ST, *p1p = m1 + 8*ST, *p2p = m2 + 8*ST, *p3p = m3 + 8*ST;
    unsigned int* op = g_M4 + w;
    float p1 = 0, q1 = 0, p2 = 0, q2 = 0;
#pragma unroll 1
    for (int t0 = 0; t0 < 296; t0 += 8) {
#pragma unroll
        for (int k = 0; k < 8; k++) {
            int cnt = ((buf[k][0] >> lane) & 1) + ((buf[k][1] >> lane) & 1)
                    + ((buf[k][2] >> lane) & 1) + ((buf[k][3] >> lane) & 1);
            buf[k][0] = *p0; p0 += ST;
            buf[k][1] = xv ? *p1p : 0u; p1p += ST;
            buf[k][2] = yv ? *p2p : 0u; p2p += ST;
            buf[k][3] = (xv && yv) ? *p3p : 0u; p3p += ST;
            float s = srm_step(p1, q1, p2, q2, 11.0f * (float)cnt);
            unsigned bal = __ballot_sync(0xffffffffu, s > 0.5f);
            if (!lane) *op = bal;
            op += NB*162;
        }
    }
#pragma unroll
    for (int k = 0; k < 4; k++) {
        int cnt = ((buf[k][0] >> lane) & 1) + ((buf[k][1] >> lane) & 1)
                + ((buf[k][2] >> lane) & 1) + ((buf[k][3] >> lane) & 1);
        float s = srm_step(p1, q1, p2, q2, 11.0f * (float)cnt);
        unsigned bal = __ballot_sync(0xffffffffu, s > 0.5f);
        if (!lane) *op = bal;
        op += NB*162;
    }
}

// ---------------- conv3 acc (48->96, 3x3, pad1, 9x9): warp per (t,b,x-PAIR), compact weights ----------------
__global__ void __launch_bounds__(256) conv3_acc() {
    int gw = blockIdx.x * 8 + (threadIdx.x >> 5);
    int lane = threadIdx.x & 31;
    if (gw >= TT*NB*45) return;                          // 9 rows x 5 pairs
    int pr = gw % 45, tb = gw / 45;
    int y = pr / 5, x0 = (pr % 5) * 2;
    bool x1v = (x0 + 1) < 9;
    const unsigned* mm = g_M4 + (size_t)tb*162;
    float a00 = 0.f, a01 = 0.f, a02 = 0.f;
    float a10 = 0.f, a11 = 0.f, a12 = 0.f;
#pragma unroll
    for (int ky = 0; ky < 3; ky++) {
        int yy = y + ky - 1;
        if (yy < 0 || yy >= 9) continue;
        const unsigned* row = mm + yy*18;
#pragma unroll
        for (int xi = 0; xi < 4; xi++) {                 // input cols x0-1 .. x0+2
            int xx = x0 - 1 + xi;
            unsigned mlo = 0u, mhi = 0u;
            if (xx >= 0 && xx < 9 && (xi < 3 || x1v)) {
                mlo = row[xx*2];
                mhi = row[xx*2 + 1];
            }
            while (mlo) {
                int c = __ffs(mlo) - 1; mlo &= mlo - 1;
                const float4* wb = g_Wt3p + c*288 + lane;
                if (xi < 3) {
                    float4 wv = wb[(ky*3 + xi)*32];
                    a00 += wv.x; a01 += wv.y; a02 += wv.z;
                }
                if (xi >= 1 && x1v) {
                    float4 wv = wb[(ky*3 + xi - 1)*32];
                    a10 += wv.x; a11 += wv.y; a12 += wv.z;
                }
            }
            while (mhi) {
                int c = __ffs(mhi) - 1; mhi &= mhi - 1;
                const float4* wb = g_Wt3p + (c + 32)*288 + lane;
                if (xi < 3) {
                    float4 wv = wb[(ky*3 + xi)*32];
                    a00 += wv.x; a01 += wv.y; a02 += wv.z;
                }
                if (xi >= 1 && x1v) {
                    float4 wv = wb[(ky*3 + xi - 1)*32];
                    a10 += wv.x; a11 += wv.y; a12 += wv.z;
                }
            }
        }
    }
    size_t base = ((size_t)tb*81 + y*9 + x0)*96;
    g_A3[base + lane]      = a00;
    g_A3[base + 32 + lane] = a01;
    g_A3[base + 64 + lane] = a02;
    if (x1v) {
        g_A3[base + 96 + lane]  = a10;
        g_A3[base + 128 + lane] = a11;
        g_A3[base + 160 + lane] = a12;
    }
}

// ---------------- pool3 + SRM fused: warp per (b,opix,wrd), PF=8, rolling ptrs ----------------
__global__ void __launch_bounds__(512) pool3_srm() {
    int w = blockIdx.x * 16 + (threadIdx.x >> 5);
    int lane = threadIdx.x & 31;
    if (w >= NB*75) return;
    int b = w / 75, r = w % 75, pix = r / 3, wrd = r % 3;
    int y = pix / 5, x = pix % 5;
    bool xv = (2*x + 1) < 9, yv = (2*y + 1) < 9;
    const int ST = 972;                                  // words per t-plane
    const unsigned* m0 = g_M5 + b*243 + (2*y*9 + 2*x)*3 + wrd;
    const unsigned* m1 = m0 + 3;
    const unsigned* m2 = m0 + 27;
    const unsigned* m3 = m0 + 30;
    unsigned buf[8][4];
#pragma unroll
    for (int k = 0; k < 8; k++) {
        buf[k][0] = m0[k*ST];
        buf[k][1] = xv ? m1[k*ST] : 0u;
        buf[k][2] = yv ? m2[k*ST] : 0u;
        buf[k][3] = (xv && yv) ? m3[k*ST] : 0u;
    }
    const unsigned *p0 = m0 + 8*ST, *p1p = m1 + 8*ST, *p2p = m2 + 8*ST, *p3p = m3 + 8*ST;
    unsigned int* op = g_M6 + w;
    float p1 = 0, q1 = 0, p2 = 0, q2 = 0;
#pragma unroll 1
    for (int t0 = 0; t0 < 296; t0 += 8) {
#pragma unroll
        for (int k = 0; k < 8; k++) {
            int cnt = ((buf[k][0] >> lane) & 1) + ((buf[k][1] >> lane) & 1)
                    + ((buf[k][2] >> lane) & 1) + ((buf[k][3] >> lane) & 1);
            buf[k][0] = *p0; p0 += ST;
            buf[k][1] = xv ? *p1p : 0u; p1p += ST;
            buf[k][2] = yv ? *p2p : 0u; p2p += ST;
            buf[k][3] = (xv && yv) ? *p3p : 0u; p3p += ST;
            float s = srm_step(p1, q1, p2, q2, 11.0f * (float)cnt);
            unsigned bal = __ballot_sync(0xffffffffu, s > 0.5f);
            if (!lane) *op = bal;
            op += NB*75;
        }
    }
#pragma unroll
    for (int k = 0; k < 4; k++) {
        int cnt = ((buf[k][0] >> lane) & 1) + ((buf[k][1] >> lane) & 1)
                + ((buf[k][2] >> lane) & 1) + ((buf[k][3] >> lane) & 1);
        float s = srm_step(p1, q1, p2, q2, 11.0f * (float)cnt);
        unsigned bal = __ballot_sync(0xffffffffu, s > 0.5f);
        if (!lane) *op = bal;
        op += NB*75;
    }
}

// ---------------- dense1 (2400->256): WARP per (t,b), float4 weight rows ----------------
__global__ void __launch_bounds__(256) dense1() {
    int w = blockIdx.x * 8 + (threadIdx.x >> 5);
    int lane = threadIdx.x & 31;
    if (w >= TT*NB) return;
    const unsigned* m = g_M6 + (size_t)w*75;
    float4 acc0 = make_float4(0.f, 0.f, 0.f, 0.f);
    float4 acc1 = make_float4(0.f, 0.f, 0.f, 0.f);
    int pw = 0;
    for (int pos = 0; pos < 25; pos++) {
#pragma unroll
        for (int wrd = 0; wrd < 3; wrd++) {
            unsigned mm = m[pw++];
            int cb = wrd*32;
            while (mm) {
                int c = cb + __ffs(mm) - 1; mm &= mm - 1;
                const float4* wr = (const float4*)(g_Wt4 + (size_t)(c*25 + pos)*256) + lane;
                float4 v0 = wr[0], v1 = wr[32];
                acc0.x += v0.x; acc0.y += v0.y; acc0.z += v0.z; acc0.w += v0.w;
                acc1.x += v1.x; acc1.y += v1.y; acc1.z += v1.z; acc1.w += v1.w;
            }
        }
    }
    float4* op = (float4*)(g_A7 + (size_t)w*256) + lane;
    op[0]  = acc0;
    op[32] = acc1;
}

// ---------------- dense2 (256->10): warp per (t,b), writes transposed ----------------
__global__ void __launch_bounds__(256) dense2() {
    int w = blockIdx.x * 8 + (threadIdx.x >> 5);
    int lane = threadIdx.x & 31;
    if (w >= TT*NB) return;
    int t = w / NB, b = w % NB;
    if (lane < 16) {
        const unsigned* m = g_M7 + (size_t)w*8;
        float acc = 0.f;
        for (int wd = 0; wd < 8; wd++) {
            unsigned mm = m[wd];
            int ib = wd*32;
            while (mm) { int i = ib + __ffs(mm) - 1; mm &= mm - 1; acc += g_Wt5[i*16 + lane]; }
        }
        g_A8T[(size_t)(b*16 + lane)*TT + t] = acc;
    }
}

// ---------------- final SRM -> output spikes (B,10,T) ----------------
__global__ void srm_out(float* __restrict__ out) {
    int tid = threadIdx.x;
    if (tid >= 40) return;
    int b = tid / 10, o = tid % 10;
    const float* ip = g_A8T + (size_t)(b*16 + o)*TT;
    const int PF = 8;
    float buf[PF];
#pragma unroll
    for (int k = 0; k < PF; k++) buf[k] = ip[k];
    float p1 = 0, q1 = 0, p2 = 0, q2 = 0;
    float* op = out + (size_t)(b*10 + o)*TT;
    for (int t0 = 0; t0 < TT; t0 += PF) {
#pragma unroll
        for (int k = 0; k < PF; k++) {
            int t = t0 + k;
            if (t >= TT) break;
            float x = buf[k];
            int tn = t + PF;
            buf[k] = (tn < TT) ? ip[tn] : 0.f;
            op[t] = srm_step(p1, q1, p2, q2, x);
        }
    }
}

extern "C" void kernel_launch(void* const* d_in, const int* in_sizes, int n_in,
                              void* d_out, int out_size) {
    const float* s_in = (const float*)d_in[0];
    const float* Wc1  = (const float*)d_in[1];
    const float* Wc2  = (const float*)d_in[2];
    const float* Wc3  = (const float*)d_in[3];
    const float* Wd4a = (const float*)d_in[4];
    const float* Wd4b = (const float*)d_in[5];
    float* out = (float*)d_out;

    // slots 0..2 so conv1_acc lands in the profiled 4th slot
    init_weights<<<54, 256>>>(Wc1, Wc2, Wc3, Wd4b);
    pack_input<<<(NB*2*34*10 + 15)/16, 512>>>(s_in);
    prep_wt4<<<dim3(75, 8), dim3(32, 8)>>>(Wd4a);

    conv1_acc<<<(TT*NB*306 + 7)/8, 256>>>();
    srm_scan_L1<<<(NB*1156 + 15)/16, 512>>>();
    pool1_srm<<<(NB*289 + 15)/16, 512>>>();

    conv2_acc<<<(TT*NB*153 + 7)/8, 256>>>();
    srm_scan_L2<<<(NB*289*2 + 15)/16, 512>>>();
    pool2_srm<<<(NB*162 + 15)/16, 512>>>();

    conv3_acc<<<(TT*NB*45 + 7)/8, 256>>>();
    srm_scan_L3<<<(NB*81*3 + 15)/16, 512>>>();
    pool3_srm<<<(NB*75 + 15)/16, 512>>>();

    dense1<<<(TT*NB + 7)/8, 256>>>();
    srm_scan_D1<<<2, 512>>>();

    dense2<<<(TT*NB + 7)/8, 256>>>();
    srm_out<<<1, 64>>>(out);
}

// round 15
// speedup vs baseline: 1.4819x; 1.0220x over previous
#include <cuda_runtime.h>

#define TT 300
#define NB 4

// ---------------- static device buffers ----------------
__device__ unsigned long long g_r0[TT*NB*2*34];                      // input row masks, bit (x+2)
__device__ unsigned int g_M2[TT*NB*289];                             // spikes P1 (17x17, 24ch)
__device__ unsigned int g_M4[TT*NB*81*2];                            // spikes P2 (9x9, 48ch/2w)
__device__ unsigned int g_M6[TT*NB*25*3];                            // spikes P3 (5x5, 96ch/3w)
__device__ unsigned int g_M7[TT*NB*8];                               // spikes dense1: 256 bits

__device__ float g_A1[(size_t)TT*NB*1156*32];                        // conv1 pre-act (pad 24->32)
__device__ float g_A2[(size_t)TT*NB*289*64];                         // conv2 pre-act (pad 48->64)
__device__ float g_A3[(size_t)TT*NB*81*96];                          // conv3 pre-act
__device__ __align__(16) float g_A7[TT*NB*256];                      // dense1 pre-act
__device__ float g_A8T[NB*16*TT];                                    // dense2 pre-act, [b][o][t]

// conv1: SCALAR zero-padded table (44 KB, L1-resident; measured best 77us)
__device__ float  g_Wt1x[5*2*11*32];    // [ky][c][u=kx+3: 0..10][o pad32]
// conv2/conv3: compact L1-resident tables
__device__ float2 g_Wt2p[216*32];       // [(c*9+kt)][lane] -> (o=lane, o=lane+32)
__device__ float4 g_Wt3p[432*32];       // [(c*9+kt)][lane] -> (o=lane, +32, +64, pad)
__device__ __align__(16) float g_Wt4[2400*256];  // [(c*25+pos)][o 256]
__device__ float  g_Wt5[256*16];        // [i][o pad16]

// ---------------- SRM step: psp (tau=10) + spike w/ refractory (tau=1) ----------------
__device__ __forceinline__ float srm_step(float& p1, float& q1, float& p2, float& q2, float x) {
    const float A1 = 0.90483741803595952f;   // exp(-1/10)
    const float C1 = 0.27182818284590452f;   // e/10
    const float A2 = 0.36787944117144233f;   // exp(-1)
    const float C2 = 2.71828182845904523f;   // e
    const float RR = 20.0f * C2;             // SCALE_REF*THETA*c
    q1 = A1*q1 + A1*p1;
    p1 = A1*p1 + x;
    float y = C1 * q1;
    q2 = A2*q2 + A2*p2;
    float u = y - RR*q2;
    float s = (u >= 10.0f) ? 1.0f : 0.0f;
    p2 = A2*p2 + s;
    return s;
}

// 5-chain SRM state: 4 conv-pixel chains + 1 pool chain per thread
struct Srm5 {
    float p1[5], q1[5], p2[5], q2[5];
    __device__ __forceinline__ void init() {
#pragma unroll
        for (int j = 0; j < 5; j++) { p1[j]=0; q1[j]=0; p2[j]=0; q2[j]=0; }
    }
    __device__ __forceinline__ float step(int j, float x) {
        return srm_step(p1[j], q1[j], p2[j], q2[j], x);
    }
};

// ---------------- fused scan+pool L1: warp=(b,opix 17x17), lane=ch; M1 never materialized ----------------
__global__ void __launch_bounds__(512) scan_pool_L1() {
    int w = blockIdx.x * 16 + (threadIdx.x >> 5);
    int lane = threadIdx.x & 31;
    if (w >= NB*289) return;
    int b = w / 289, pix = w % 289;
    int y = pix / 17, x = pix % 17;
    int p00 = 2*y*34 + 2*x;                              // all 4 pixels valid (34 even)
    const size_t S = (size_t)NB*1156*32;                 // per-t stride
    const float* base = g_A1 + (size_t)b*1156*32 + lane;
    const float* s0 = base + (size_t)p00*32;
    const float* s1 = s0 + 32;
    const float* s2 = s0 + 34*32;
    const float* s3 = s0 + 35*32;
    const int PF = 6;
    float buf[PF][4];
#pragma unroll
    for (int k = 0; k < PF; k++) {
        buf[k][0] = s0[k*S]; buf[k][1] = s1[k*S];
        buf[k][2] = s2[k*S]; buf[k][3] = s3[k*S];
    }
    const float *f0 = s0 + PF*S, *f1 = s1 + PF*S, *f2 = s2 + PF*S, *f3 = s3 + PF*S;
    unsigned int* op = g_M2 + w;
    Srm5 st; st.init();
#pragma unroll 1
    for (int t0 = 0; t0 < TT - PF; t0 += PF) {           // 294 main steps
#pragma unroll
        for (int k = 0; k < PF; k++) {
            float v0 = buf[k][0], v1 = buf[k][1], v2 = buf[k][2], v3 = buf[k][3];
            buf[k][0] = *f0; f0 += S;
            buf[k][1] = *f1; f1 += S;
            buf[k][2] = *f2; f2 += S;
            buf[k][3] = *f3; f3 += S;
            float c0 = st.step(0, v0), c1 = st.step(1, v1);
            float c2 = st.step(2, v2), c3 = st.step(3, v3);
            float sp = st.step(4, 11.0f * (c0 + c1 + c2 + c3));
            unsigned bal = __ballot_sync(0xffffffffu, sp > 0.5f);
            if (!lane) *op = bal;
            op += NB*289;
        }
    }
#pragma unroll
    for (int k = 0; k < PF; k++) {                       // t = 294..299
        float c0 = st.step(0, buf[k][0]), c1 = st.step(1, buf[k][1]);
        float c2 = st.step(2, buf[k][2]), c3 = st.step(3, buf[k][3]);
        float sp = st.step(4, 11.0f * (c0 + c1 + c2 + c3));
        unsigned bal = __ballot_sync(0xffffffffu, sp > 0.5f);
        if (!lane) *op = bal;
        op += NB*289;
    }
}

// ---------------- fused scan+pool L2: warp=(b,opix 9x9,half), lane=ch in half ----------------
__global__ void __launch_bounds__(512) scan_pool_L2() {
    int w = blockIdx.x * 16 + (threadIdx.x >> 5);
    int lane = threadIdx.x & 31;
    if (w >= NB*162) return;
    int b = w / 162, r = w % 162, pix = r >> 1, half = r & 1;
    int y = pix / 9, x = pix % 9;
    float fx = ((2*x + 1) < 17) ? 1.f : 0.f;
    float fy = ((2*y + 1) < 17) ? 1.f : 0.f;
    float fxy = fx * fy;
    int p00 = 2*y*17 + 2*x;
    const size_t S = (size_t)NB*289*64;
    const float* base = g_A2 + (size_t)b*289*64 + half*32 + lane;
    const float* s0 = base + (size_t)p00*64;
    const float* s1 = s0 + 64;                           // may be OOB pixel -> zeroed by fx
    const float* s2 = s0 + 17*64;
    const float* s3 = s0 + 18*64;
    if (fx == 0.f)  s1 = s0;
    if (fy == 0.f)  s2 = s0;
    if (fxy == 0.f) s3 = s0;
    const int PF = 6;
    float buf[PF][4];
#pragma unroll
    for (int k = 0; k < PF; k++) {
        buf[k][0] = s0[k*S];      buf[k][1] = s1[k*S]*fx;
        buf[k][2] = s2[k*S]*fy;   buf[k][3] = s3[k*S]*fxy;
    }
    const float *f0 = s0 + PF*S, *f1 = s1 + PF*S, *f2 = s2 + PF*S, *f3 = s3 + PF*S;
    unsigned int* op = g_M4 + w;
    Srm5 st; st.init();
#pragma unroll 1
    for (int t0 = 0; t0 < TT - PF; t0 += PF) {
#pragma unroll
        for (int k = 0; k < PF; k++) {
            float v0 = buf[k][0], v1 = buf[k][1], v2 = buf[k][2], v3 = buf[k][3];
            buf[k][0] = *f0;       f0 += S;
            buf[k][1] = (*f1)*fx;  f1 += S;
            buf[k][2] = (*f2)*fy;  f2 += S;
            buf[k][3] = (*f3)*fxy; f3 += S;
            float c0 = st.step(0, v0), c1 = st.step(1, v1);
            float c2 = st.step(2, v2), c3 = st.step(3, v3);
            float sp = st.step(4, 11.0f * (c0 + c1 + c2 + c3));
            unsigned bal = __ballot_sync(0xffffffffu, sp > 0.5f);
            if (!lane) *op = bal;
            op += NB*162;
        }
    }
#pragma unroll
    for (int k = 0; k < PF; k++) {
        float c0 = st.step(0, buf[k][0]), c1 = st.step(1, buf[k][1]);
        float c2 = st.step(2, buf[k][2]), c3 = st.step(3, buf[k][3]);
        float sp = st.step(4, 11.0f * (c0 + c1 + c2 + c3));
        unsigned bal = __ballot_sync(0xffffffffu, sp > 0.5f);
        if (!lane) *op = bal;
        op += NB*162;
    }
}

// ---------------- fused scan+pool L3: warp=(b,opix 5x5,wrd), lane=ch in wrd ----------------
__global__ void __launch_bounds__(512) scan_pool_L3() {
    int w = blockIdx.x * 16 + (threadIdx.x >> 5);
    int lane = threadIdx.x & 31;
    if (w >= NB*75) return;
    int b = w / 75, r = w % 75, pix = r / 3, wrd = r % 3;
    int y = pix / 5, x = pix % 5;
    float fx = ((2*x + 1) < 9) ? 1.f : 0.f;
    float fy = ((2*y + 1) < 9) ? 1.f : 0.f;
    float fxy = fx * fy;
    int p00 = 2*y*9 + 2*x;
    const size_t S = (size_t)NB*81*96;
    const float* base = g_A3 + (size_t)b*81*96 + wrd*32 + lane;
    const float* s0 = base + (size_t)p00*96;
    const float* s1 = s0 + 96;
    const float* s2 = s0 + 9*96;
    const float* s3 = s0 + 10*96;
    if (fx == 0.f)  s1 = s0;
    if (fy == 0.f)  s2 = s0;
    if (fxy == 0.f) s3 = s0;
    const int PF = 6;
    float buf[PF][4];
#pragma unroll
    for (int k = 0; k < PF; k++) {
        buf[k][0] = s0[k*S];      buf[k][1] = s1[k*S]*fx;
        buf[k][2] = s2[k*S]*fy;   buf[k][3] = s3[k*S]*fxy;
    }
    const float *f0 = s0 + PF*S, *f1 = s1 + PF*S, *f2 = s2 + PF*S, *f3 = s3 + PF*S;
    unsigned int* op = g_M6 + w;
    Srm5 st; st.init();
#pragma unroll 1
    for (int t0 = 0; t0 < TT - PF; t0 += PF) {
#pragma unroll
        for (int k = 0; k < PF; k++) {
            float v0 = buf[k][0], v1 = buf[k][1], v2 = buf[k][2], v3 = buf[k][3];
            buf[k][0] = *f0;       f0 += S;
            buf[k][1] = (*f1)*fx;  f1 += S;
            buf[k][2] = (*f2)*fy;  f2 += S;
            buf[k][3] = (*f3)*fxy; f3 += S;
            float c0 = st.step(0, v0), c1 = st.step(1, v1);
            float c2 = st.step(2, v2), c3 = st.step(3, v3);
            float sp = st.step(4, 11.0f * (c0 + c1 + c2 + c3));
            unsigned bal = __ballot_sync(0xffffffffu, sp > 0.5f);
            if (!lane) *op = bal;
            op += NB*75;
        }
    }
#pragma unroll
    for (int k = 0; k < PF; k++) {
        float c0 = st.step(0, buf[k][0]), c1 = st.step(1, buf[k][1]);
        float c2 = st.step(2, buf[k][2]), c3 = st.step(3, buf[k][3]);
        float sp = st.step(4, 11.0f * (c0 + c1 + c2 + c3));
        unsigned bal = __ballot_sync(0xffffffffu, sp > 0.5f);
        if (!lane) *op = bal;
        op += NB*75;
    }
}

// ---------------- SRM scan for dense1 (A7 -> M7) ----------------
__global__ void __launch_bounds__(512) srm_scan_D1() {
    int w = blockIdx.x * 16 + (threadIdx.x >> 5);
    int lane = threadIdx.x & 31;
    const int nW = NB*8;
    if (w >= nW) return;
    size_t S = (size_t)nW * 32;
    const float* ip = g_A7 + (size_t)w*32 + lane;
    const int PF = 12;
    float buf[PF];
#pragma unroll
    for (int k = 0; k < PF; k++) buf[k] = ip[(size_t)k*S];
    const float* pf = ip + (size_t)PF*S;
    unsigned int* op = g_M7 + w;
    float p1=0,q1=0,p2=0,q2=0;
#pragma unroll 1
    for (int t0 = 0; t0 < TT - PF; t0 += PF) {
#pragma unroll
        for (int k = 0; k < PF; k++) {
            float x = buf[k];
            buf[k] = *pf; pf += S;
            float s = srm_step(p1, q1, p2, q2, x);
            unsigned bal = __ballot_sync(0xffffffffu, s > 0.5f);
            if (!lane) *op = bal;
            op += nW;
        }
    }
#pragma unroll
    for (int k = 0; k < PF; k++) {
        float s = srm_step(p1, q1, p2, q2, buf[k]);
        unsigned bal = __ballot_sync(0xffffffffu, s > 0.5f);
        if (!lane) *op = bal;
        op += nW;
    }
}

// ---------------- init: weight tables ----------------
__global__ void init_weights(const float* __restrict__ Wc1, const float* __restrict__ Wc2,
                             const float* __restrict__ Wc3, const float* __restrict__ Wd4b) {
    int i = blockIdx.x * 256 + threadIdx.x;
    if (i < 5*2*11*32) {                                 // conv1 scalar padded table
        int q = i >> 5, o = i & 31;
        int ky = q / 22, rem = q % 22, c = rem / 11, u = rem % 11;
        int kx = u - 3;
        g_Wt1x[i] = (o < 24 && kx >= 0 && kx < 5) ? Wc1[o*50 + c*25 + ky*5 + kx] : 0.f;
    }
    if (i < 216*32) {                                    // conv2 compact
        int tap = i >> 5, l = i & 31;
        float x = Wc2[l*216 + tap];
        float y = (l < 16) ? Wc2[(l + 32)*216 + tap] : 0.f;
        g_Wt2p[i] = make_float2(x, y);
    }
    if (i < 432*32) {                                    // conv3 compact
        int tap = i >> 5, l = i & 31;
        g_Wt3p[i] = make_float4(Wc3[l*432 + tap], Wc3[(l + 32)*432 + tap],
                                Wc3[(l + 64)*432 + tap], 0.f);
    }
    if (i < 256*16) {
        int r = i >> 4, o = i & 15;
        g_Wt5[i] = (o < 10) ? Wd4b[o*256 + r] : 0.f;
    }
}

// ---------------- pack s_in -> row bitmasks; warp=(b,c,y,t-chunk), lane=t: coalesced ----------------
__global__ void __launch_bounds__(512) pack_input(const float* __restrict__ s_in) {
    int w = blockIdx.x * 16 + (threadIdx.x >> 5);
    int lane = threadIdx.x & 31;
    if (w >= NB*2*34*10) return;
    int chunk = w % 10;
    int r = w / 10;
    int y = r % 34; r /= 34;
    int c = r % 2;
    int b = r / 2;
    int t = chunk * 32 + lane;
    bool tv = t < TT;
    const float* sp = s_in + ((size_t)((b*2 + c)*34 + y)*34)*TT + (tv ? t : 0);
    unsigned long long m = 0ull;
#pragma unroll
    for (int x = 0; x < 34; x++) {
        float v = sp[(size_t)x*TT];                      // lane-coalesced along t
        m |= (unsigned long long)(v != 0.f) << (x + 2);
    }
    if (tv) g_r0[((size_t)(t*NB + b)*2 + c)*34 + y] = m;
}

// ---------------- coalesced smem-tiled transpose of Wd4a -> g_Wt4 ----------------
__global__ void prep_wt4(const float* __restrict__ Wd4a) {
    __shared__ float tile[32][33];
    int r0 = blockIdx.x * 32, o0 = blockIdx.y * 32;
    int tx = threadIdx.x, ty = threadIdx.y;              // 32 x 8
#pragma unroll
    for (int j = 0; j < 32; j += 8)
        tile[ty + j][tx] = Wd4a[(size_t)(o0 + ty + j)*2400 + r0 + tx];   // coalesced in r
    __syncthreads();
#pragma unroll
    for (int j = 0; j < 32; j += 8)
        g_Wt4[(size_t)(r0 + ty + j)*256 + o0 + tx] = tile[tx][ty + j];   // coalesced in o
}

// ---------------- conv1 acc: warp per (t,b,x-QUAD), event-direct, scalar padded weights ----------------
__global__ void __launch_bounds__(256) conv1_acc() {
    int gw = blockIdx.x * 8 + (threadIdx.x >> 5);
    int lane = threadIdx.x & 31;
    if (gw >= TT*NB*306) return;                         // 34 rows x 9 quads
    int pr = gw % 306, tb = gw / 306;
    int y = pr / 9, x0 = (pr % 9) * 4;
    const unsigned long long* rt = g_r0 + (size_t)tb*68;
    const float* wl = g_Wt1x + lane;
    float a0 = 0.f, a1 = 0.f, a2 = 0.f, a3 = 0.f;
#pragma unroll
    for (int ky = 0; ky < 5; ky++) {
        int yy = y + ky - 2;
        if (yy < 0 || yy >= 34) continue;
        unsigned w0 = (unsigned)(rt[yy] >> x0) & 0xFFu;        // taps for pixels x0..x0+3, c=0
        unsigned w1 = (unsigned)(rt[34 + yy] >> x0) & 0xFFu;   // c=1
        unsigned f = w0 | (w1 << 8);
        if (!f) continue;                                // early-out: common at 3% density
        const float* wk = wl + ky*704;                   // ky*2*11*32
        do {
            int bit = __ffs(f) - 1; f &= f - 1;
            int c = bit >> 3, j = bit & 7;               // j = input col - x0
            const float* wr = wk + c*352 + (j << 5);     // slot u=j (kx = j - p -> u = j-p+3)
            a3 += wr[0];                                 // p=3: u=j
            a2 += wr[32];                                // p=2: u=j+1
            a1 += wr[64];                                // p=1: u=j+2
            a0 += wr[96];                                // p=0: u=j+3
        } while (f);
    }
    size_t base = ((size_t)tb*1156 + y*34 + x0)*32;
    g_A1[base + lane]      = a0;
    g_A1[base + 32 + lane] = a1;
    if (x0 + 2 < 34) {                                   // last quad has only 2 valid pixels
        g_A1[base + 64 + lane] = a2;
        g_A1[base + 96 + lane] = a3;
    }
}

// ---------------- conv2 acc (24->48, 3x3, pad1, 17x17): warp per (t,b,x-PAIR), compact weights ----------------
__global__ void __launch_bounds__(256) conv2_acc() {
    int gw = blockIdx.x * 8 + (threadIdx.x >> 5);
    int lane = threadIdx.x & 31;
    if (gw >= TT*NB*153) return;                         // 17 rows x 9 pairs
    int pr = gw % 153, tb = gw / 153;
    int y = pr / 9, x0 = (pr % 9) * 2;
    bool x1v = (x0 + 1) < 17;
    const unsigned* mm = g_M2 + (size_t)tb*289;
    float aa0 = 0.f, ab0 = 0.f, aa1 = 0.f, ab1 = 0.f;
#pragma unroll
    for (int ky = 0; ky < 3; ky++) {
        int yy = y + ky - 1;
        if (yy < 0 || yy >= 17) continue;
        const unsigned* row = mm + yy*17;
#pragma unroll
        for (int xi = 0; xi < 4; xi++) {                 // input cols x0-1 .. x0+2
            int xx = x0 - 1 + xi;
            unsigned m = 0u;
            if (xx >= 0 && xx < 17 && (xi < 3 || x1v)) m = row[xx];
            while (m) {
                int c = __ffs(m) - 1; m &= m - 1;
                const float2* wb = g_Wt2p + c*288 + lane;     // c*9*32
                if (xi < 3) {                                 // pixel0: kt = ky*3+xi
                    float2 wv = wb[(ky*3 + xi)*32];
                    aa0 += wv.x; ab0 += wv.y;
                }
                if (xi >= 1 && x1v) {                         // pixel1: kt = ky*3+xi-1
                    float2 wv = wb[(ky*3 + xi - 1)*32];
                    aa1 += wv.x; ab1 += wv.y;
                }
            }
        }
    }
    size_t base = ((size_t)tb*289 + y*17 + x0)*64;
    g_A2[base + lane]      = aa0;
    g_A2[base + 32 + lane] = ab0;
    if (x1v) {
        g_A2[base + 64 + lane] = aa1;
        g_A2[base + 96 + lane] = ab1;
    }
}

// ---------------- conv3 acc (48->96, 3x3, pad1, 9x9): warp per (t,b,x-PAIR), compact weights ----------------
__global__ void __launch_bounds__(256) conv3_acc() {
    int gw = blockIdx.x * 8 + (threadIdx.x >> 5);
    int lane = threadIdx.x & 31;
    if (gw >= TT*NB*45) return;                          // 9 rows x 5 pairs
    int pr = gw % 45, tb = gw / 45;
    int y = pr / 5, x0 = (pr % 5) * 2;
    bool x1v = (x0 + 1) < 9;
    const unsigned* mm = g_M4 + (size_t)tb*162;
    float a00 = 0.f, a01 = 0.f, a02 = 0.f;
    float a10 = 0.f, a11 = 0.f, a12 = 0.f;
#pragma unroll
    for (int ky = 0; ky < 3; ky++) {
        int yy = y + ky - 1;
        if (yy < 0 || yy >= 9) continue;
        const unsigned* row = mm + yy*18;
#pragma unroll
        for (int xi = 0; xi < 4; xi++) {                 // input cols x0-1 .. x0+2
            int xx = x0 - 1 + xi;
            unsigned mlo = 0u, mhi = 0u;
            if (xx >= 0 && xx < 9 && (xi < 3 || x1v)) {
                mlo = row[xx*2];
                mhi = row[xx*2 + 1];
            }
            while (mlo) {
                int c = __ffs(mlo) - 1; mlo &= mlo - 1;
                const float4* wb = g_Wt3p + c*288 + lane;
                if (xi < 3) {
                    float4 wv = wb[(ky*3 + xi)*32];
                    a00 += wv.x; a01 += wv.y; a02 += wv.z;
                }
                if (xi >= 1 && x1v) {
                    float4 wv = wb[(ky*3 + xi - 1)*32];
                    a10 += wv.x; a11 += wv.y; a12 += wv.z;
                }
            }
            while (mhi) {
                int c = __ffs(mhi) - 1; mhi &= mhi - 1;
                const float4* wb = g_Wt3p + (c + 32)*288 + lane;
                if (xi < 3) {
                    float4 wv = wb[(ky*3 + xi)*32];
                    a00 += wv.x; a01 += wv.y; a02 += wv.z;
                }
                if (xi >= 1 && x1v) {
                    float4 wv = wb[(ky*3 + xi - 1)*32];
                    a10 += wv.x; a11 += wv.y; a12 += wv.z;
                }
            }
        }
    }
    size_t base = ((size_t)tb*81 + y*9 + x0)*96;
    g_A3[base + lane]      = a00;
    g_A3[base + 32 + lane] = a01;
    g_A3[base + 64 + lane] = a02;
    if (x1v) {
        g_A3[base + 96 + lane]  = a10;
        g_A3[base + 128 + lane] = a11;
        g_A3[base + 160 + lane] = a12;
    }
}

// ---------------- dense1 (2400->256): WARP per (t,b), float4 weight rows ----------------
__global__ void __launch_bounds__(256) dense1() {
    int w = blockIdx.x * 8 + (threadIdx.x >> 5);
    int lane = threadIdx.x & 31;
    if (w >= TT*NB) return;
    const unsigned* m = g_M6 + (size_t)w*75;
    float4 acc0 = make_float4(0.f, 0.f, 0.f, 0.f);
    float4 acc1 = make_float4(0.f, 0.f, 0.f, 0.f);
    int pw = 0;
    for (int pos = 0; pos < 25; pos++) {
#pragma unroll
        for (int wrd = 0; wrd < 3; wrd++) {
            unsigned mm = m[pw++];
            int cb = wrd*32;
            while (mm) {
                int c = cb + __ffs(mm) - 1; mm &= mm - 1;
                const float4* wr = (const float4*)(g_Wt4 + (size_t)(c*25 + pos)*256) + lane;
                float4 v0 = wr[0], v1 = wr[32];
                acc0.x += v0.x; acc0.y += v0.y; acc0.z += v0.z; acc0.w += v0.w;
                acc1.x += v1.x; acc1.y += v1.y; acc1.z += v1.z; acc1.w += v1.w;
            }
        }
    }
    float4* op = (float4*)(g_A7 + (size_t)w*256) + lane;
    op[0]  = acc0;
    op[32] = acc1;
}

// ---------------- dense2 (256->10): warp per (t,b), writes transposed ----------------
__global__ void __launch_bounds__(256) dense2() {
    int w = blockIdx.x * 8 + (threadIdx.x >> 5);
    int lane = threadIdx.x & 31;
    if (w >= TT*NB) return;
    int t = w / NB, b = w % NB;
    if (lane < 16) {
        const unsigned* m = g_M7 + (size_t)w*8;
        float acc = 0.f;
        for (int wd = 0; wd < 8; wd++) {
            unsigned mm = m[wd];
            int ib = wd*32;
            while (mm) { int i = ib + __ffs(mm) - 1; mm &= mm - 1; acc += g_Wt5[i*16 + lane]; }
        }
        g_A8T[(size_t)(b*16 + lane)*TT + t] = acc;
    }
}

// ---------------- final SRM -> output spikes (B,10,T) ----------------
__global__ void srm_out(float* __restrict__ out) {
    int tid = threadIdx.x;
    if (tid >= 40) return;
    int b = tid / 10, o = tid % 10;
    const float* ip = g_A8T + (size_t)(b*16 + o)*TT;
    const int PF = 8;
    float buf[PF];
#pragma unroll
    for (int k = 0; k < PF; k++) buf[k] = ip[k];
    float p1 = 0, q1 = 0, p2 = 0, q2 = 0;
    float* op = out + (size_t)(b*10 + o)*TT;
    for (int t0 = 0; t0 < TT; t0 += PF) {
#pragma unroll
        for (int k = 0; k < PF; k++) {
            int t = t0 + k;
            if (t >= TT) break;
            float x = buf[k];
            int tn = t + PF;
            buf[k] = (tn < TT) ? ip[tn] : 0.f;
            op[t] = srm_step(p1, q1, p2, q2, x);
        }
    }
}

extern "C" void kernel_launch(void* const* d_in, const int* in_sizes, int n_in,
                              void* d_out, int out_size) {
    const float* s_in = (const float*)d_in[0];
    const float* Wc1  = (const float*)d_in[1];
    const float* Wc2  = (const float*)d_in[2];
    const float* Wc3  = (const float*)d_in[3];
    const float* Wd4a = (const float*)d_in[4];
    const float* Wd4b = (const float*)d_in[5];
    float* out = (float*)d_out;

    // slots 0..2 so conv1_acc lands in the profiled 4th slot (stable control)
    init_weights<<<54, 256>>>(Wc1, Wc2, Wc3, Wd4b);
    pack_input<<<(NB*2*34*10 + 15)/16, 512>>>(s_in);
    prep_wt4<<<dim3(75, 8), dim3(32, 8)>>>(Wd4a);

    conv1_acc<<<(TT*NB*306 + 7)/8, 256>>>();
    scan_pool_L1<<<(NB*289 + 15)/16, 512>>>();

    conv2_acc<<<(TT*NB*153 + 7)/8, 256>>>();
    scan_pool_L2<<<(NB*162 + 15)/16, 512>>>();

    conv3_acc<<<(TT*NB*45 + 7)/8, 256>>>();
    scan_pool_L3<<<(NB*75 + 15)/16, 512>>>();

    dense1<<<(TT*NB + 7)/8, 256>>>();
    srm_scan_D1<<<2, 512>>>();

    dense2<<<(TT*NB + 7)/8, 256>>>();
    srm_out<<<1, 64>>>(out);
}

// round 16
// speedup vs baseline: 1.6090x; 1.0857x over previous
#include <cuda_runtime.h>

#define TT 300
#define NB 4

// ---------------- static device buffers ----------------
__device__ unsigned long long g_r0[TT*NB*2*34];                      // input row masks, bit (x+2)
__device__ unsigned int g_M2[TT*NB*289];                             // spikes P1 (17x17, 24ch)
__device__ unsigned int g_M4[TT*NB*81*2];                            // spikes P2 (9x9, 48ch/2w)
__device__ unsigned int g_M6[TT*NB*25*3];                            // spikes P3 (5x5, 96ch/3w)
__device__ unsigned int g_M7[TT*NB*8];                               // spikes dense1: 256 bits

__device__ float g_A1[(size_t)TT*NB*1156*32];                        // conv1 pre-act (pad 24->32)
__device__ float g_A2[(size_t)TT*NB*289*64];                         // conv2 pre-act (pad 48->64)
__device__ float g_A3[(size_t)TT*NB*81*96];                          // conv3 pre-act
__device__ __align__(16) float g_A7[TT*NB*256];                      // dense1 pre-act
__device__ float g_A8T[NB*16*TT];                                    // dense2 pre-act, [b][o][t]

// conv1: SCALAR zero-padded table (44 KB, L1-resident; measured best 77us)
__device__ float  g_Wt1x[5*2*11*32];    // [ky][c][u=kx+3: 0..10][o pad32]
// conv2/conv3: compact L1-resident tables
__device__ float2 g_Wt2p[216*32];       // [(c*9+kt)][lane] -> (o=lane, o=lane+32)
__device__ float4 g_Wt3p[432*32];       // [(c*9+kt)][lane] -> (o=lane, +32, +64, pad)
__device__ __align__(16) float g_Wt4[2400*256];  // [(c*25+pos)][o 256]
__device__ float  g_Wt5[256*16];        // [i][o pad16]

// ---------------- SRM step: psp (tau=10) + spike w/ refractory (tau=1) ----------------
__device__ __forceinline__ float srm_step(float& p1, float& q1, float& p2, float& q2, float x) {
    const float A1 = 0.90483741803595952f;   // exp(-1/10)
    const float C1 = 0.27182818284590452f;   // e/10
    const float A2 = 0.36787944117144233f;   // exp(-1)
    const float C2 = 2.71828182845904523f;   // e
    const float RR = 20.0f * C2;             // SCALE_REF*THETA*c
    q1 = A1*q1 + A1*p1;
    p1 = A1*p1 + x;
    float y = C1 * q1;
    q2 = A2*q2 + A2*p2;
    float u = y - RR*q2;
    float s = (u >= 10.0f) ? 1.0f : 0.0f;
    p2 = A2*p2 + s;
    return s;
}

// 5-chain SRM state: 4 conv-pixel chains + 1 pool chain per thread
struct Srm5 {
    float p1[5], q1[5], p2[5], q2[5];
    __device__ __forceinline__ void init() {
#pragma unroll
        for (int j = 0; j < 5; j++) { p1[j]=0; q1[j]=0; p2[j]=0; q2[j]=0; }
    }
    __device__ __forceinline__ float step(int j, float x) {
        return srm_step(p1[j], q1[j], p2[j], q2[j], x);
    }
};

// ---------------- init: weight tables + input bit-pack (merged) ----------------
__global__ void __launch_bounds__(512) init_all(const float* __restrict__ Wc1,
                                               const float* __restrict__ Wc2,
                                               const float* __restrict__ Wc3,
                                               const float* __restrict__ Wd4b,
                                               const float* __restrict__ s_in) {
    int bid = blockIdx.x;
    if (bid < 27) {
        int i = bid * 512 + threadIdx.x;
        if (i < 5*2*11*32) {                             // conv1 scalar padded table
            int q = i >> 5, o = i & 31;
            int ky = q / 22, rem = q % 22, c = rem / 11, u = rem % 11;
            int kx = u - 3;
            g_Wt1x[i] = (o < 24 && kx >= 0 && kx < 5) ? Wc1[o*50 + c*25 + ky*5 + kx] : 0.f;
        }
        if (i < 216*32) {                                // conv2 compact
            int tap = i >> 5, l = i & 31;
            float x = Wc2[l*216 + tap];
            float y = (l < 16) ? Wc2[(l + 32)*216 + tap] : 0.f;
            g_Wt2p[i] = make_float2(x, y);
        }
        if (i < 432*32) {                                // conv3 compact
            int tap = i >> 5, l = i & 31;
            g_Wt3p[i] = make_float4(Wc3[l*432 + tap], Wc3[(l + 32)*432 + tap],
                                    Wc3[(l + 64)*432 + tap], 0.f);
        }
        if (i < 256*16) {
            int r = i >> 4, o = i & 15;
            g_Wt5[i] = (o < 10) ? Wd4b[o*256 + r] : 0.f;
        }
    } else {
        int w = (bid - 27) * 16 + (threadIdx.x >> 5);
        int lane = threadIdx.x & 31;
        if (w >= NB*2*34*10) return;
        int chunk = w % 10;
        int r = w / 10;
        int y = r % 34; r /= 34;
        int c = r % 2;
        int b = r / 2;
        int t = chunk * 32 + lane;
        bool tv = t < TT;
        const float* sp = s_in + ((size_t)((b*2 + c)*34 + y)*34)*TT + (tv ? t : 0);
        unsigned long long m = 0ull;
#pragma unroll
        for (int x = 0; x < 34; x++) {
            float v = sp[(size_t)x*TT];                  // lane-coalesced along t
            m |= (unsigned long long)(v != 0.f) << (x + 2);
        }
        if (tv) g_r0[((size_t)(t*NB + b)*2 + c)*34 + y] = m;
    }
}

// ---------------- coalesced smem-tiled transpose of Wd4a -> g_Wt4 ----------------
__global__ void prep_wt4(const float* __restrict__ Wd4a) {
    __shared__ float tile[32][33];
    int r0 = blockIdx.x * 32, o0 = blockIdx.y * 32;
    int tx = threadIdx.x, ty = threadIdx.y;              // 32 x 8
#pragma unroll
    for (int j = 0; j < 32; j += 8)
        tile[ty + j][tx] = Wd4a[(size_t)(o0 + ty + j)*2400 + r0 + tx];   // coalesced in r
    __syncthreads();
#pragma unroll
    for (int j = 0; j < 32; j += 8)
        g_Wt4[(size_t)(r0 + ty + j)*256 + o0 + tx] = tile[tx][ty + j];   // coalesced in o
}

// ---------------- conv1 acc: warp per (t,b,x-QUAD), event-direct, scalar padded weights ----------------
__global__ void __launch_bounds__(256) conv1_acc() {
    int gw = blockIdx.x * 8 + (threadIdx.x >> 5);
    int lane = threadIdx.x & 31;
    if (gw >= TT*NB*306) return;                         // 34 rows x 9 quads
    int pr = gw % 306, tb = gw / 306;
    int y = pr / 9, x0 = (pr % 9) * 4;
    const unsigned long long* rt = g_r0 + (size_t)tb*68;
    const float* wl = g_Wt1x + lane;
    float a0 = 0.f, a1 = 0.f, a2 = 0.f, a3 = 0.f;
#pragma unroll
    for (int ky = 0; ky < 5; ky++) {
        int yy = y + ky - 2;
        if (yy < 0 || yy >= 34) continue;
        unsigned w0 = (unsigned)(rt[yy] >> x0) & 0xFFu;        // taps for pixels x0..x0+3, c=0
        unsigned w1 = (unsigned)(rt[34 + yy] >> x0) & 0xFFu;   // c=1
        unsigned f = w0 | (w1 << 8);
        if (!f) continue;                                // early-out: common at 3% density
        const float* wk = wl + ky*704;                   // ky*2*11*32
        do {
            int bit = __ffs(f) - 1; f &= f - 1;
            int c = bit >> 3, j = bit & 7;               // j = input col - x0
            const float* wr = wk + c*352 + (j << 5);     // slot u=j (kx = j - p -> u = j-p+3)
            a3 += wr[0];                                 // p=3: u=j
            a2 += wr[32];                                // p=2: u=j+1
            a1 += wr[64];                                // p=1: u=j+2
            a0 += wr[96];                                // p=0: u=j+3
        } while (f);
    }
    size_t base = ((size_t)tb*1156 + y*34 + x0)*32;
    g_A1[base + lane]      = a0;
    g_A1[base + 32 + lane] = a1;
    if (x0 + 2 < 34) {                                   // last quad has only 2 valid pixels
        g_A1[base + 64 + lane] = a2;
        g_A1[base + 96 + lane] = a3;
    }
}

// ---------------- fused scan+pool L1: warp=(b,opix 17x17), lane=ch ----------------
__global__ void __launch_bounds__(512) scan_pool_L1() {
    int w = blockIdx.x * 16 + (threadIdx.x >> 5);
    int lane = threadIdx.x & 31;
    if (w >= NB*289) return;
    int b = w / 289, pix = w % 289;
    int y = pix / 17, x = pix % 17;
    int p00 = 2*y*34 + 2*x;                              // all 4 pixels valid (34 even)
    const size_t S = (size_t)NB*1156*32;                 // per-t stride
    const float* base = g_A1 + (size_t)b*1156*32 + lane;
    const float* s0 = base + (size_t)p00*32;
    const float* s1 = s0 + 32;
    const float* s2 = s0 + 34*32;
    const float* s3 = s0 + 35*32;
    const int PF = 6;
    float buf[PF][4];
#pragma unroll
    for (int k = 0; k < PF; k++) {
        buf[k][0] = s0[k*S]; buf[k][1] = s1[k*S];
        buf[k][2] = s2[k*S]; buf[k][3] = s3[k*S];
    }
    const float *f0 = s0 + PF*S, *f1 = s1 + PF*S, *f2 = s2 + PF*S, *f3 = s3 + PF*S;
    unsigned int* op = g_M2 + w;
    Srm5 st; st.init();
#pragma unroll 1
    for (int t0 = 0; t0 < TT - PF; t0 += PF) {           // 294 main steps
#pragma unroll
        for (int k = 0; k < PF; k++) {
            float v0 = buf[k][0], v1 = buf[k][1], v2 = buf[k][2], v3 = buf[k][3];
            buf[k][0] = *f0; f0 += S;
            buf[k][1] = *f1; f1 += S;
            buf[k][2] = *f2; f2 += S;
            buf[k][3] = *f3; f3 += S;
            float c0 = st.step(0, v0), c1 = st.step(1, v1);
            float c2 = st.step(2, v2), c3 = st.step(3, v3);
            float sp = st.step(4, 11.0f * (c0 + c1 + c2 + c3));
            unsigned bal = __ballot_sync(0xffffffffu, sp > 0.5f);
            if (!lane) *op = bal;
            op += NB*289;
        }
    }
#pragma unroll
    for (int k = 0; k < PF; k++) {                       // t = 294..299
        float c0 = st.step(0, buf[k][0]), c1 = st.step(1, buf[k][1]);
        float c2 = st.step(2, buf[k][2]), c3 = st.step(3, buf[k][3]);
        float sp = st.step(4, 11.0f * (c0 + c1 + c2 + c3));
        unsigned bal = __ballot_sync(0xffffffffu, sp > 0.5f);
        if (!lane) *op = bal;
        op += NB*289;
    }
}

// ---------------- conv2 acc (24->48, 3x3, pad1, 17x17): warp per (t,b,x-QUAD) ----------------
__global__ void __launch_bounds__(256) conv2_acc() {
    int gw = blockIdx.x * 8 + (threadIdx.x >> 5);
    int lane = threadIdx.x & 31;
    if (gw >= TT*NB*85) return;                          // 17 rows x 5 quads
    int pr = gw % 85, tb = gw / 85;
    int y = pr / 5, x0 = (pr % 5) * 4;
    bool pv1 = (x0 + 1) < 17, pv2 = (x0 + 2) < 17, pv3 = (x0 + 3) < 17;
    const unsigned* mm = g_M2 + (size_t)tb*289;
    float aa0=0.f, ab0=0.f, aa1=0.f, ab1=0.f, aa2=0.f, ab2=0.f, aa3=0.f, ab3=0.f;
#pragma unroll
    for (int ky = 0; ky < 3; ky++) {
        int yy = y + ky - 1;
        if (yy < 0 || yy >= 17) continue;
        const unsigned* row = mm + yy*17;
#pragma unroll
        for (int xi = 0; xi < 6; xi++) {                 // input cols x0-1 .. x0+4
            int xx = x0 - 1 + xi;
            bool need = (xi < 4) || (xi == 4 ? pv2 : pv3);
            unsigned m = 0u;
            if (xx >= 0 && xx < 17 && need) m = row[xx];
            while (m) {
                int c = __ffs(m) - 1; m &= m - 1;
                const float2* wb = g_Wt2p + c*288 + lane;       // c*9*32
                // pixel p gets tap kt = ky*3 + (xi-p), valid for p in [xi-2, xi] ∩ [0,3]
                if (xi <= 2)                 { float2 wv = wb[(ky*3 + xi)*32];     aa0 += wv.x; ab0 += wv.y; }
                if (xi >= 1 && xi <= 3 && pv1){ float2 wv = wb[(ky*3 + xi - 1)*32]; aa1 += wv.x; ab1 += wv.y; }
                if (xi >= 2 && xi <= 4 && pv2){ float2 wv = wb[(ky*3 + xi - 2)*32]; aa2 += wv.x; ab2 += wv.y; }
                if (xi >= 3 && pv3)           { float2 wv = wb[(ky*3 + xi - 3)*32]; aa3 += wv.x; ab3 += wv.y; }
            }
        }
    }
    size_t base = ((size_t)tb*289 + y*17 + x0)*64;
    g_A2[base + lane]      = aa0;
    g_A2[base + 32 + lane] = ab0;
    if (pv1) { g_A2[base + 64 + lane]  = aa1; g_A2[base + 96 + lane]  = ab1; }
    if (pv2) { g_A2[base + 128 + lane] = aa2; g_A2[base + 160 + lane] = ab2; }
    if (pv3) { g_A2[base + 192 + lane] = aa3; g_A2[base + 224 + lane] = ab3; }
}

// ---------------- fused scan+pool L2: warp=(b,opix 9x9,half), lane=ch in half ----------------
__global__ void __launch_bounds__(512) scan_pool_L2() {
    int w = blockIdx.x * 16 + (threadIdx.x >> 5);
    int lane = threadIdx.x & 31;
    if (w >= NB*162) return;
    int b = w / 162, r = w % 162, pix = r >> 1, half = r & 1;
    int y = pix / 9, x = pix % 9;
    float fx = ((2*x + 1) < 17) ? 1.f : 0.f;
    float fy = ((2*y + 1) < 17) ? 1.f : 0.f;
    float fxy = fx * fy;
    int p00 = 2*y*17 + 2*x;
    const size_t S = (size_t)NB*289*64;
    const float* base = g_A2 + (size_t)b*289*64 + half*32 + lane;
    const float* s0 = base + (size_t)p00*64;
    const float* s1 = s0 + 64;
    const float* s2 = s0 + 17*64;
    const float* s3 = s0 + 18*64;
    if (fx == 0.f)  s1 = s0;
    if (fy == 0.f)  s2 = s0;
    if (fxy == 0.f) s3 = s0;
    const int PF = 6;
    float buf[PF][4];
#pragma unroll
    for (int k = 0; k < PF; k++) {
        buf[k][0] = s0[k*S];      buf[k][1] = s1[k*S]*fx;
        buf[k][2] = s2[k*S]*fy;   buf[k][3] = s3[k*S]*fxy;
    }
    const float *f0 = s0 + PF*S, *f1 = s1 + PF*S, *f2 = s2 + PF*S, *f3 = s3 + PF*S;
    unsigned int* op = g_M4 + w;
    Srm5 st; st.init();
#pragma unroll 1
    for (int t0 = 0; t0 < TT - PF; t0 += PF) {
#pragma unroll
        for (int k = 0; k < PF; k++) {
            float v0 = buf[k][0], v1 = buf[k][1], v2 = buf[k][2], v3 = buf[k][3];
            buf[k][0] = *f0;       f0 += S;
            buf[k][1] = (*f1)*fx;  f1 += S;
            buf[k][2] = (*f2)*fy;  f2 += S;
            buf[k][3] = (*f3)*fxy; f3 += S;
            float c0 = st.step(0, v0), c1 = st.step(1, v1);
            float c2 = st.step(2, v2), c3 = st.step(3, v3);
            float sp = st.step(4, 11.0f * (c0 + c1 + c2 + c3));
            unsigned bal = __ballot_sync(0xffffffffu, sp > 0.5f);
            if (!lane) *op = bal;
            op += NB*162;
        }
    }
#pragma unroll
    for (int k = 0; k < PF; k++) {
        float c0 = st.step(0, buf[k][0]), c1 = st.step(1, buf[k][1]);
        float c2 = st.step(2, buf[k][2]), c3 = st.step(3, buf[k][3]);
        float sp = st.step(4, 11.0f * (c0 + c1 + c2 + c3));
        unsigned bal = __ballot_sync(0xffffffffu, sp > 0.5f);
        if (!lane) *op = bal;
        op += NB*162;
    }
}

// ---------------- conv3 acc (48->96, 3x3, pad1, 9x9): warp per (t,b,x-QUAD) ----------------
__global__ void __launch_bounds__(256) conv3_acc() {
    int gw = blockIdx.x * 8 + (threadIdx.x >> 5);
    int lane = threadIdx.x & 31;
    if (gw >= TT*NB*27) return;                          // 9 rows x 3 quads
    int pr = gw % 27, tb = gw / 27;
    int y = pr / 3, x0 = (pr % 3) * 4;
    bool pv1 = (x0 + 1) < 9, pv2 = (x0 + 2) < 9, pv3 = (x0 + 3) < 9;
    const unsigned* mm = g_M4 + (size_t)tb*162;
    float a0x=0.f,a0y=0.f,a0z=0.f, a1x=0.f,a1y=0.f,a1z=0.f;
    float a2x=0.f,a2y=0.f,a2z=0.f, a3x=0.f,a3y=0.f,a3z=0.f;
#pragma unroll
    for (int ky = 0; ky < 3; ky++) {
        int yy = y + ky - 1;
        if (yy < 0 || yy >= 9) continue;
        const unsigned* row = mm + yy*18;
#pragma unroll
        for (int xi = 0; xi < 6; xi++) {                 // input cols x0-1 .. x0+4
            int xx = x0 - 1 + xi;
            bool need = (xi < 4) || (xi == 4 ? pv2 : pv3);
            unsigned mlo = 0u, mhi = 0u;
            if (xx >= 0 && xx < 9 && need) {
                mlo = row[xx*2];
                mhi = row[xx*2 + 1];
            }
            while (mlo) {
                int c = __ffs(mlo) - 1; mlo &= mlo - 1;
                const float4* wb = g_Wt3p + c*288 + lane;
                if (xi <= 2)                  { float4 wv = wb[(ky*3 + xi)*32];     a0x += wv.x; a0y += wv.y; a0z += wv.z; }
                if (xi >= 1 && xi <= 3 && pv1){ float4 wv = wb[(ky*3 + xi - 1)*32]; a1x += wv.x; a1y += wv.y; a1z += wv.z; }
                if (xi >= 2 && xi <= 4 && pv2){ float4 wv = wb[(ky*3 + xi - 2)*32]; a2x += wv.x; a2y += wv.y; a2z += wv.z; }
                if (xi >= 3 && pv3)           { float4 wv = wb[(ky*3 + xi - 3)*32]; a3x += wv.x; a3y += wv.y; a3z += wv.z; }
            }
            while (mhi) {
                int c = __ffs(mhi) - 1; mhi &= mhi - 1;
                const float4* wb = g_Wt3p + (c + 32)*288 + lane;
                if (xi <= 2)                  { float4 wv = wb[(ky*3 + xi)*32];     a0x += wv.x; a0y += wv.y; a0z += wv.z; }
                if (xi >= 1 && xi <= 3 && pv1){ float4 wv = wb[(ky*3 + xi - 1)*32]; a1x += wv.x; a1y += wv.y; a1z += wv.z; }
                if (xi >= 2 && xi <= 4 && pv2){ float4 wv = wb[(ky*3 + xi - 2)*32]; a2x += wv.x; a2y += wv.y; a2z += wv.z; }
                if (xi >= 3 && pv3)           { float4 wv = wb[(ky*3 + xi - 3)*32]; a3x += wv.x; a3y += wv.y; a3z += wv.z; }
            }
        }
    }
    size_t base = ((size_t)tb*81 + y*9 + x0)*96;
    g_A3[base + lane]      = a0x;
    g_A3[base + 32 + lane] = a0y;
    g_A3[base + 64 + lane] = a0z;
    if (pv1) { g_A3[base + 96  + lane] = a1x; g_A3[base + 128 + lane] = a1y; g_A3[base + 160 + lane] = a1z; }
    if (pv2) { g_A3[base + 192 + lane] = a2x; g_A3[base + 224 + lane] = a2y; g_A3[base + 256 + lane] = a2z; }
    if (pv3) { g_A3[base + 288 + lane] = a3x; g_A3[base + 320 + lane] = a3y; g_A3[base + 352 + lane] = a3z; }
}

// ---------------- fused scan+pool L3: warp=(b,opix 5x5,wrd), lane=ch in wrd ----------------
__global__ void __launch_bounds__(512) scan_pool_L3() {
    int w = blockIdx.x * 16 + (threadIdx.x >> 5);
    int lane = threadIdx.x & 31;
    if (w >= NB*75) return;
    int b = w / 75, r = w % 75, pix = r / 3, wrd = r % 3;
    int y = pix / 5, x = pix % 5;
    float fx = ((2*x + 1) < 9) ? 1.f : 0.f;
    float fy = ((2*y + 1) < 9) ? 1.f : 0.f;
    float fxy = fx * fy;
    int p00 = 2*y*9 + 2*x;
    const size_t S = (size_t)NB*81*96;
    const float* base = g_A3 + (size_t)b*81*96 + wrd*32 + lane;
    const float* s0 = base + (size_t)p00*96;
    const float* s1 = s0 + 96;
    const float* s2 = s0 + 9*96;
    const float* s3 = s0 + 10*96;
    if (fx == 0.f)  s1 = s0;
    if (fy == 0.f)  s2 = s0;
    if (fxy == 0.f) s3 = s0;
    const int PF = 6;
    float buf[PF][4];
#pragma unroll
    for (int k = 0; k < PF; k++) {
        buf[k][0] = s0[k*S];      buf[k][1] = s1[k*S]*fx;
        buf[k][2] = s2[k*S]*fy;   buf[k][3] = s3[k*S]*fxy;
    }
    const float *f0 = s0 + PF*S, *f1 = s1 + PF*S, *f2 = s2 + PF*S, *f3 = s3 + PF*S;
    unsigned int* op = g_M6 + w;
    Srm5 st; st.init();
#pragma unroll 1
    for (int t0 = 0; t0 < TT - PF; t0 += PF) {
#pragma unroll
        for (int k = 0; k < PF; k++) {
            float v0 = buf[k][0], v1 = buf[k][1], v2 = buf[k][2], v3 = buf[k][3];
            buf[k][0] = *f0;       f0 += S;
            buf[k][1] = (*f1)*fx;  f1 += S;
            buf[k][2] = (*f2)*fy;  f2 += S;
            buf[k][3] = (*f3)*fxy; f3 += S;
            float c0 = st.step(0, v0), c1 = st.step(1, v1);
            float c2 = st.step(2, v2), c3 = st.step(3, v3);
            float sp = st.step(4, 11.0f * (c0 + c1 + c2 + c3));
            unsigned bal = __ballot_sync(0xffffffffu, sp > 0.5f);
            if (!lane) *op = bal;
            op += NB*75;
        }
    }
#pragma unroll
    for (int k = 0; k < PF; k++) {
        float c0 = st.step(0, buf[k][0]), c1 = st.step(1, buf[k][1]);
        float c2 = st.step(2, buf[k][2]), c3 = st.step(3, buf[k][3]);
        float sp = st.step(4, 11.0f * (c0 + c1 + c2 + c3));
        unsigned bal = __ballot_sync(0xffffffffu, sp > 0.5f);
        if (!lane) *op = bal;
        op += NB*75;
    }
}

// ---------------- dense1 (2400->256): WARP per (t,b), float4 weight rows ----------------
__global__ void __launch_bounds__(256) dense1() {
    int w = blockIdx.x * 8 + (threadIdx.x >> 5);
    int lane = threadIdx.x & 31;
    if (w >= TT*NB) return;
    const unsigned* m = g_M6 + (size_t)w*75;
    float4 acc0 = make_float4(0.f, 0.f, 0.f, 0.f);
    float4 acc1 = make_float4(0.f, 0.f, 0.f, 0.f);
    int pw = 0;
    for (int pos = 0; pos < 25; pos++) {
#pragma unroll
        for (int wrd = 0; wrd < 3; wrd++) {
            unsigned mm = m[pw++];
            int cb = wrd*32;
            while (mm) {
                int c = cb + __ffs(mm) - 1; mm &= mm - 1;
                const float4* wr = (const float4*)(g_Wt4 + (size_t)(c*25 + pos)*256) + lane;
                float4 v0 = wr[0], v1 = wr[32];
                acc0.x += v0.x; acc0.y += v0.y; acc0.z += v0.z; acc0.w += v0.w;
                acc1.x += v1.x; acc1.y += v1.y; acc1.z += v1.z; acc1.w += v1.w;
            }
        }
    }
    float4* op = (float4*)(g_A7 + (size_t)w*256) + lane;
    op[0]  = acc0;
    op[32] = acc1;
}

// ---------------- SRM scan for dense1 (A7 -> M7) ----------------
__global__ void __launch_bounds__(512) srm_scan_D1() {
    int w = blockIdx.x * 16 + (threadIdx.x >> 5);
    int lane = threadIdx.x & 31;
    const int nW = NB*8;
    if (w >= nW) return;
    size_t S = (size_t)nW * 32;
    const float* ip = g_A7 + (size_t)w*32 + lane;
    const int PF = 12;
    float buf[PF];
#pragma unroll
    for (int k = 0; k < PF; k++) buf[k] = ip[(size_t)k*S];
    const float* pf = ip + (size_t)PF*S;
    unsigned int* op = g_M7 + w;
    float p1=0,q1=0,p2=0,q2=0;
#pragma unroll 1
    for (int t0 = 0; t0 < TT - PF; t0 += PF) {
#pragma unroll
        for (int k = 0; k < PF; k++) {
            float x = buf[k];
            buf[k] = *pf; pf += S;
            float s = srm_step(p1, q1, p2, q2, x);
            unsigned bal = __ballot_sync(0xffffffffu, s > 0.5f);
            if (!lane) *op = bal;
            op += nW;
        }
    }
#pragma unroll
    for (int k = 0; k < PF; k++) {
        float s = srm_step(p1, q1, p2, q2, buf[k]);
        unsigned bal = __ballot_sync(0xffffffffu, s > 0.5f);
        if (!lane) *op = bal;
        op += nW;
    }
}

// ---------------- dense2 (256->10): warp per (t,b), writes transposed ----------------
__global__ void __launch_bounds__(256) dense2() {
    int w = blockIdx.x * 8 + (threadIdx.x >> 5);
    int lane = threadIdx.x & 31;
    if (w >= TT*NB) return;
    int t = w / NB, b = w % NB;
    if (lane < 16) {
        const unsigned* m = g_M7 + (size_t)w*8;
        float acc = 0.f;
        for (int wd = 0; wd < 8; wd++) {
            unsigned mm = m[wd];
            int ib = wd*32;
            while (mm) { int i = ib + __ffs(mm) - 1; mm &= mm - 1; acc += g_Wt5[i*16 + lane]; }
        }
        g_A8T[(size_t)(b*16 + lane)*TT + t] = acc;
    }
}

// ---------------- final SRM -> output spikes (B,10,T) ----------------
__global__ void srm_out(float* __restrict__ out) {
    int tid = threadIdx.x;
    if (tid >= 40) return;
    int b = tid / 10, o = tid % 10;
    const float* ip = g_A8T + (size_t)(b*16 + o)*TT;
    const int PF = 8;
    float buf[PF];
#pragma unroll
    for (int k = 0; k < PF; k++) buf[k] = ip[k];
    float p1 = 0, q1 = 0, p2 = 0, q2 = 0;
    float* op = out + (size_t)(b*10 + o)*TT;
    for (int t0 = 0; t0 < TT; t0 += PF) {
#pragma unroll
        for (int k = 0; k < PF; k++) {
            int t = t0 + k;
            if (t >= TT) break;
            float x = buf[k];
            int tn = t + PF;
            buf[k] = (tn < TT) ? ip[tn] : 0.f;
            op[t] = srm_step(p1, q1, p2, q2, x);
        }
    }
}

extern "C" void kernel_launch(void* const* d_in, const int* in_sizes, int n_in,
                              void* d_out, int out_size) {
    const float* s_in = (const float*)d_in[0];
    const float* Wc1  = (const float*)d_in[1];
    const float* Wc2  = (const float*)d_in[2];
    const float* Wc3  = (const float*)d_in[3];
    const float* Wd4a = (const float*)d_in[4];
    const float* Wd4b = (const float*)d_in[5];
    float* out = (float*)d_out;

    // conv2_acc is the 4th launch -> it lands in the ncu profile slot this round
    init_all<<<27 + (NB*2*34*10 + 15)/16, 512>>>(Wc1, Wc2, Wc3, Wd4b, s_in);
    conv1_acc<<<(TT*NB*306 + 7)/8, 256>>>();
    scan_pool_L1<<<(NB*289 + 15)/16, 512>>>();

    conv2_acc<<<(TT*NB*85 + 7)/8, 256>>>();
    scan_pool_L2<<<(NB*162 + 15)/16, 512>>>();

    conv3_acc<<<(TT*NB*27 + 7)/8, 256>>>();
    scan_pool_L3<<<(NB*75 + 15)/16, 512>>>();

    prep_wt4<<<dim3(75, 8), dim3(32, 8)>>>(Wd4a);
    dense1<<<(TT*NB + 7)/8, 256>>>();
    srm_scan_D1<<<2, 512>>>();

    dense2<<<(TT*NB + 7)/8, 256>>>();
    srm_out<<<1, 64>>>(out);
}